// round 2
// baseline (speedup 1.0000x reference)
#include <cuda_runtime.h>

#define BT 16
#define HH 48
#define WW 48
#define C 64
#define HEADS 8
#define HD 8
#define KS 7
#define NPIX (BT*HH*WW)   /* 36864 */
#define QSCALE 0.35355339059327373f

// Scratch (static device allocations are allowed)
__device__ float g_Q[NPIX*C];
__device__ float g_K[NPIX*C];
__device__ float g_V[NPIX*C];
__device__ float g_A[NPIX*C];

// ---------------------------------------------------------------------------
// Kernel 1: QKV projection. qkv[n,o] = sum_c x[n,c]*w[o,c] + b[o]
// Block = 256 threads (8 warps), 32 rows per block.
// Lane = row (x from padded smem, conflict-free float4), o uniform per warp
// iteration (weight loads are uniform broadcasts, L1-resident 48KB).
// ---------------------------------------------------------------------------
__global__ __launch_bounds__(256) void qkv_kernel(const float* __restrict__ x,
                                                  const float* __restrict__ w,
                                                  const float* __restrict__ b) {
    __shared__ float xs[32*76];   // pad 76 floats/row -> conflict-free LDS.128
    int row0 = blockIdx.x * 32;
    const float4* x4 = (const float4*)(x + (size_t)row0 * C);
    for (int idx = threadIdx.x; idx < 512; idx += 256) {   // 32 rows * 16 f4
        int r = idx >> 4, c4 = idx & 15;
        ((float4*)xs)[r*19 + c4] = x4[idx];
    }
    __syncthreads();

    int warp = threadIdx.x >> 5, lane = threadIdx.x & 31;
    int row = row0 + lane;
    const float4* w4 = (const float4*)w;
    const float4* xr = ((const float4*)xs) + lane*19;

    float4 xv[16];
    #pragma unroll
    for (int cc = 0; cc < 16; cc++) xv[cc] = xr[cc];

    #pragma unroll 4
    for (int t = 0; t < 24; t++) {
        int o = warp*24 + t;                 // uniform across lanes
        float acc = 0.f;
        #pragma unroll
        for (int cc = 0; cc < 16; cc++) {
            float4 wv = __ldg(&w4[o*16 + cc]);
            acc += xv[cc].x*wv.x + xv[cc].y*wv.y + xv[cc].z*wv.z + xv[cc].w*wv.w;
        }
        acc += __ldg(&b[o]);
        if (o < 64)        g_Q[(size_t)row*C + o]         = acc * QSCALE;
        else if (o < 128)  g_K[(size_t)row*C + (o - 64)]  = acc;
        else               g_V[(size_t)row*C + (o - 128)] = acc;
    }
}

// ---------------------------------------------------------------------------
// Kernel 2: neighborhood attention. One thread per (pixel, head).
// Block = 256 threads = 32 pixels x 8 heads. Scores live in registers.
// ---------------------------------------------------------------------------
__global__ __launch_bounds__(256) void attn_kernel(const float* __restrict__ rpb) {
    __shared__ float rpb_s[HEADS*13*13];
    for (int idx = threadIdx.x; idx < HEADS*169; idx += 256) rpb_s[idx] = rpb[idx];
    __syncthreads();

    int head  = threadIdx.x & 7;
    int pixel = blockIdx.x*32 + (threadIdx.x >> 3);
    int bt  = pixel / (HH*WW);
    int rem = pixel - bt*(HH*WW);
    int i = rem / WW, j = rem - i*WW;
    int si = min(max(i - 3, 0), HH - KS);
    int sj = min(max(j - 3, 0), WW - KS);

    const float4* Q4 = (const float4*)g_Q;
    const float4* K4 = (const float4*)g_K;
    const float4* V4 = (const float4*)g_V;

    int qi = pixel*16 + head*2;
    float4 qa = Q4[qi], qb = Q4[qi+1];

    int base = bt*(HH*WW)*16 + head*2;
    const float* rp = rpb_s + head*169 + (si - i + 6)*13 + (sj - j + 6);

    float sc[49];
    float m = -1e30f;
    #pragma unroll
    for (int pr = 0; pr < 7; pr++) {
        int rb = base + (si + pr)*WW*16 + sj*16;
        #pragma unroll
        for (int pc = 0; pc < 7; pc++) {
            int a = rb + pc*16;
            float4 ka = K4[a], kb = K4[a+1];
            float s = qa.x*ka.x + qa.y*ka.y + qa.z*ka.z + qa.w*ka.w
                    + qb.x*kb.x + qb.y*kb.y + qb.z*kb.z + qb.w*kb.w;
            s += rp[pr*13 + pc];
            sc[pr*7 + pc] = s;
            m = fmaxf(m, s);
        }
    }

    float sum = 0.f;
    #pragma unroll
    for (int p = 0; p < 49; p++) {
        float e = __expf(sc[p] - m);
        sc[p] = e;
        sum += e;
    }

    float4 oa = make_float4(0.f,0.f,0.f,0.f);
    float4 ob = make_float4(0.f,0.f,0.f,0.f);
    #pragma unroll
    for (int pr = 0; pr < 7; pr++) {
        int rb = base + (si + pr)*WW*16 + sj*16;
        #pragma unroll
        for (int pc = 0; pc < 7; pc++) {
            int a = rb + pc*16;
            float4 va = V4[a], vb = V4[a+1];
            float e = sc[pr*7 + pc];
            oa.x += e*va.x; oa.y += e*va.y; oa.z += e*va.z; oa.w += e*va.w;
            ob.x += e*vb.x; ob.y += e*vb.y; ob.z += e*vb.z; ob.w += e*vb.w;
        }
    }

    float inv = 1.f / sum;
    oa.x *= inv; oa.y *= inv; oa.z *= inv; oa.w *= inv;
    ob.x *= inv; ob.y *= inv; ob.z *= inv; ob.w *= inv;
    float4* A4 = (float4*)g_A;
    A4[qi]   = oa;
    A4[qi+1] = ob;
}

// ---------------------------------------------------------------------------
// Kernel 3: output projection + LayerNorm. Warp per row; lane computes
// channels {lane, lane+32}; warp-shuffle reduction for mean/var.
// ---------------------------------------------------------------------------
__global__ __launch_bounds__(256) void proj_ln_kernel(const float* __restrict__ pw,
                                                      const float* __restrict__ pb,
                                                      const float* __restrict__ lng,
                                                      const float* __restrict__ lnb,
                                                      float* __restrict__ out) {
    __shared__ float pws[64*76];  // padded, conflict-free LDS.128
    __shared__ float xsm[8*64];

    const float4* pw4 = (const float4*)pw;
    for (int idx = threadIdx.x; idx < 1024; idx += 256) {   // 64 rows * 16 f4
        int r = idx >> 4, c4 = idx & 15;
        ((float4*)pws)[r*19 + c4] = pw4[idx];
    }

    int warp = threadIdx.x >> 5, lane = threadIdx.x & 31;
    int row = blockIdx.x*8 + warp;
    if (lane < 16)
        ((float4*)xsm)[warp*16 + lane] = ((const float4*)g_A)[row*16 + lane];
    __syncthreads();

    const float4* xr = (const float4*)(xsm + warp*64);
    int c0 = lane, c1 = lane + 32;
    const float4* w0p = ((const float4*)pws) + c0*19;
    const float4* w1p = ((const float4*)pws) + c1*19;

    float y0 = 0.f, y1 = 0.f;
    #pragma unroll
    for (int cc = 0; cc < 16; cc++) {
        float4 xv = xr[cc];
        float4 w0 = w0p[cc];
        float4 w1 = w1p[cc];
        y0 += xv.x*w0.x + xv.y*w0.y + xv.z*w0.z + xv.w*w0.w;
        y1 += xv.x*w1.x + xv.y*w1.y + xv.z*w1.z + xv.w*w1.w;
    }
    y0 += __ldg(&pb[c0]);
    y1 += __ldg(&pb[c1]);

    float s  = y0 + y1;
    float sq = y0*y0 + y1*y1;
    #pragma unroll
    for (int off = 16; off; off >>= 1) {
        s  += __shfl_xor_sync(0xffffffffu, s,  off);
        sq += __shfl_xor_sync(0xffffffffu, sq, off);
    }
    float mu  = s  * (1.f/64.f);
    float var = sq * (1.f/64.f) - mu*mu;
    float rs  = rsqrtf(var + 1e-5f);

    out[(size_t)row*64 + c0] = (y0 - mu)*rs*__ldg(&lng[c0]) + __ldg(&lnb[c0]);
    out[(size_t)row*64 + c1] = (y1 - mu)*rs*__ldg(&lng[c1]) + __ldg(&lnb[c1]);
}

// ---------------------------------------------------------------------------
extern "C" void kernel_launch(void* const* d_in, const int* in_sizes, int n_in,
                              void* d_out, int out_size) {
    const float* q      = (const float*)d_in[0];
    const float* qkv_w  = (const float*)d_in[1];
    const float* qkv_b  = (const float*)d_in[2];
    const float* proj_w = (const float*)d_in[3];
    const float* proj_b = (const float*)d_in[4];
    const float* rpb    = (const float*)d_in[5];
    const float* ln_g   = (const float*)d_in[6];
    const float* ln_b   = (const float*)d_in[7];

    qkv_kernel<<<NPIX/32, 256>>>(q, qkv_w, qkv_b);
    attn_kernel<<<NPIX/32, 256>>>(rpb);
    proj_ln_kernel<<<NPIX/8, 256>>>(proj_w, proj_b, ln_g, ln_b, (float*)d_out);
}

// round 4
// speedup vs baseline: 1.5028x; 1.5028x over previous
#include <cuda_runtime.h>

#define BT 16
#define HH 48
#define WW 48
#define C 64
#define HEADS 8
#define HD 8
#define KS 7
#define NPIX (BT*HH*WW)   /* 36864 */
#define QSCALE 0.35355339059327373f
#define QROWS 64

// Scratch (static device allocations are allowed)
__device__ float g_Q[NPIX*C];
__device__ float g_K[NPIX*C];
__device__ float g_V[NPIX*C];
__device__ float g_A[NPIX*C];

// ---------------------------------------------------------------------------
// Kernel 1: QKV projection. qkv[n,o] = sum_c x[n,c]*w[o,c] + b[o]
// 192 threads/block; thread owns output column o (weights in 64 registers,
// loaded once). 64 rows per block; x rows broadcast from smem (uniform LDS,
// conflict-free). Stores fully coalesced (warp = 32 consecutive columns).
// ---------------------------------------------------------------------------
__global__ __launch_bounds__(192) void qkv_kernel(const float* __restrict__ x,
                                                  const float* __restrict__ w,
                                                  const float* __restrict__ b) {
    __shared__ float xs[QROWS*64];   // 16KB
    int o = threadIdx.x;             // 0..191, the output column
    int row0 = blockIdx.x * QROWS;

    // Weight row for this output column -> registers (read once per block)
    float wr[64];
    const float4* w4 = (const float4*)(w + o*64);
    #pragma unroll
    for (int cc = 0; cc < 16; cc++) {
        float4 t = __ldg(&w4[cc]);
        wr[4*cc+0] = t.x; wr[4*cc+1] = t.y; wr[4*cc+2] = t.z; wr[4*cc+3] = t.w;
    }
    float bias = __ldg(&b[o]);

    // Stage x rows (coalesced float4 loads)
    const float4* x4 = (const float4*)(x + (size_t)row0 * 64);
    for (int idx = threadIdx.x; idx < QROWS*16; idx += 192)
        ((float4*)xs)[idx] = x4[idx];
    __syncthreads();

    // Destination select (uniform within each warp: 32 | o-boundaries)
    float* dst; float scale;
    if (o < 64)        { dst = g_Q; scale = QSCALE; dst += (size_t)row0*64 + o; }
    else if (o < 128)  { dst = g_K; scale = 1.f;    dst += (size_t)row0*64 + (o-64); }
    else               { dst = g_V; scale = 1.f;    dst += (size_t)row0*64 + (o-128); }

    #pragma unroll 2
    for (int r = 0; r < QROWS; r++) {
        const float4* xr = (const float4*)(xs + r*64);
        float a0 = 0.f, a1 = 0.f, a2 = 0.f, a3 = 0.f;
        #pragma unroll
        for (int cc = 0; cc < 16; cc += 4) {
            float4 v0 = xr[cc+0], v1 = xr[cc+1], v2 = xr[cc+2], v3 = xr[cc+3];
            a0 += wr[4*cc+ 0]*v0.x + wr[4*cc+ 1]*v0.y + wr[4*cc+ 2]*v0.z + wr[4*cc+ 3]*v0.w;
            a1 += wr[4*cc+ 4]*v1.x + wr[4*cc+ 5]*v1.y + wr[4*cc+ 6]*v1.z + wr[4*cc+ 7]*v1.w;
            a2 += wr[4*cc+ 8]*v2.x + wr[4*cc+ 9]*v2.y + wr[4*cc+10]*v2.z + wr[4*cc+11]*v2.w;
            a3 += wr[4*cc+12]*v3.x + wr[4*cc+13]*v3.y + wr[4*cc+14]*v3.z + wr[4*cc+15]*v3.w;
        }
        dst[(size_t)r*64] = ((a0 + a1) + (a2 + a3) + bias) * scale;
    }
}

// ---------------------------------------------------------------------------
// Kernel 2: neighborhood attention. One thread per (pixel, head).
// Block = 256 threads = 32 pixels x 8 heads. Scores live in registers.
// ---------------------------------------------------------------------------
__global__ __launch_bounds__(256) void attn_kernel(const float* __restrict__ rpb) {
    __shared__ float rpb_s[HEADS*13*13];
    for (int idx = threadIdx.x; idx < HEADS*169; idx += 256) rpb_s[idx] = rpb[idx];
    __syncthreads();

    int head  = threadIdx.x & 7;
    int pixel = blockIdx.x*32 + (threadIdx.x >> 3);
    int bt  = pixel / (HH*WW);
    int rem = pixel - bt*(HH*WW);
    int i = rem / WW, j = rem - i*WW;
    int si = min(max(i - 3, 0), HH - KS);
    int sj = min(max(j - 3, 0), WW - KS);

    const float4* Q4 = (const float4*)g_Q;
    const float4* K4 = (const float4*)g_K;
    const float4* V4 = (const float4*)g_V;

    int qi = pixel*16 + head*2;
    float4 qa = Q4[qi], qb = Q4[qi+1];

    int base = bt*(HH*WW)*16 + head*2;
    const float* rp = rpb_s + head*169 + (si - i + 6)*13 + (sj - j + 6);

    float sc[49];
    float m = -1e30f;
    #pragma unroll
    for (int pr = 0; pr < 7; pr++) {
        int rb = base + (si + pr)*WW*16 + sj*16;
        #pragma unroll
        for (int pc = 0; pc < 7; pc++) {
            int a = rb + pc*16;
            float4 ka = K4[a], kb = K4[a+1];
            float s = qa.x*ka.x + qa.y*ka.y + qa.z*ka.z + qa.w*ka.w
                    + qb.x*kb.x + qb.y*kb.y + qb.z*kb.z + qb.w*kb.w;
            s += rp[pr*13 + pc];
            sc[pr*7 + pc] = s;
            m = fmaxf(m, s);
        }
    }

    float sum = 0.f;
    #pragma unroll
    for (int p = 0; p < 49; p++) {
        float e = __expf(sc[p] - m);
        sc[p] = e;
        sum += e;
    }

    float4 oa = make_float4(0.f,0.f,0.f,0.f);
    float4 ob = make_float4(0.f,0.f,0.f,0.f);
    #pragma unroll
    for (int pr = 0; pr < 7; pr++) {
        int rb = base + (si + pr)*WW*16 + sj*16;
        #pragma unroll
        for (int pc = 0; pc < 7; pc++) {
            int a = rb + pc*16;
            float4 va = V4[a], vb = V4[a+1];
            float e = sc[pr*7 + pc];
            oa.x += e*va.x; oa.y += e*va.y; oa.z += e*va.z; oa.w += e*va.w;
            ob.x += e*vb.x; ob.y += e*vb.y; ob.z += e*vb.z; ob.w += e*vb.w;
        }
    }

    float inv = 1.f / sum;
    oa.x *= inv; oa.y *= inv; oa.z *= inv; oa.w *= inv;
    ob.x *= inv; ob.y *= inv; ob.z *= inv; ob.w *= inv;
    float4* A4 = (float4*)g_A;
    A4[qi]   = oa;
    A4[qi+1] = ob;
}

// ---------------------------------------------------------------------------
// Kernel 3: output projection + LayerNorm. Warp per row; lane computes
// channels {lane, lane+32}; warp-shuffle reduction for mean/var.
// ---------------------------------------------------------------------------
__global__ __launch_bounds__(256) void proj_ln_kernel(const float* __restrict__ pw,
                                                      const float* __restrict__ pb,
                                                      const float* __restrict__ lng,
                                                      const float* __restrict__ lnb,
                                                      float* __restrict__ out) {
    __shared__ float pws[64*76];  // padded, conflict-free LDS.128
    __shared__ float xsm[8*64];

    const float4* pw4 = (const float4*)pw;
    for (int idx = threadIdx.x; idx < 1024; idx += 256) {   // 64 rows * 16 f4
        int r = idx >> 4, c4 = idx & 15;
        ((float4*)pws)[r*19 + c4] = pw4[idx];
    }

    int warp = threadIdx.x >> 5, lane = threadIdx.x & 31;
    int row = blockIdx.x*8 + warp;
    if (lane < 16)
        ((float4*)xsm)[warp*16 + lane] = ((const float4*)g_A)[row*16 + lane];
    __syncthreads();

    const float4* xr = (const float4*)(xsm + warp*64);
    int c0 = lane, c1 = lane + 32;
    const float4* w0p = ((const float4*)pws) + c0*19;
    const float4* w1p = ((const float4*)pws) + c1*19;

    float y0 = 0.f, y1 = 0.f;
    #pragma unroll
    for (int cc = 0; cc < 16; cc++) {
        float4 xv = xr[cc];
        float4 w0 = w0p[cc];
        float4 w1 = w1p[cc];
        y0 += xv.x*w0.x + xv.y*w0.y + xv.z*w0.z + xv.w*w0.w;
        y1 += xv.x*w1.x + xv.y*w1.y + xv.z*w1.z + xv.w*w1.w;
    }
    y0 += __ldg(&pb[c0]);
    y1 += __ldg(&pb[c1]);

    float s  = y0 + y1;
    float sq = y0*y0 + y1*y1;
    #pragma unroll
    for (int off = 16; off; off >>= 1) {
        s  += __shfl_xor_sync(0xffffffffu, s,  off);
        sq += __shfl_xor_sync(0xffffffffu, sq, off);
    }
    float mu  = s  * (1.f/64.f);
    float var = sq * (1.f/64.f) - mu*mu;
    float rs  = rsqrtf(var + 1e-5f);

    out[(size_t)row*64 + c0] = (y0 - mu)*rs*__ldg(&lng[c0]) + __ldg(&lnb[c0]);
    out[(size_t)row*64 + c1] = (y1 - mu)*rs*__ldg(&lng[c1]) + __ldg(&lnb[c1]);
}

// ---------------------------------------------------------------------------
extern "C" void kernel_launch(void* const* d_in, const int* in_sizes, int n_in,
                              void* d_out, int out_size) {
    const float* q      = (const float*)d_in[0];
    const float* qkv_w  = (const float*)d_in[1];
    const float* qkv_b  = (const float*)d_in[2];
    const float* proj_w = (const float*)d_in[3];
    const float* proj_b = (const float*)d_in[4];
    const float* rpb    = (const float*)d_in[5];
    const float* ln_g   = (const float*)d_in[6];
    const float* ln_b   = (const float*)d_in[7];

    qkv_kernel<<<NPIX/QROWS, 192>>>(q, qkv_w, qkv_b);
    attn_kernel<<<NPIX/32, 256>>>(rpb);
    proj_ln_kernel<<<NPIX/8, 256>>>(proj_w, proj_b, ln_g, ln_b, (float*)d_out);
}

// round 5
// speedup vs baseline: 1.6075x; 1.0696x over previous
#include <cuda_runtime.h>

#define BT 16
#define HH 48
#define WW 48
#define NPIX (BT*HH*WW)   /* 36864 */
#define QSCALE 0.35355339059327373f

// Scratch (static device allocations are allowed)
__device__ float g_Q[NPIX*64];
__device__ float g_K[NPIX*64];
__device__ float g_V[NPIX*64];

// ---------------------------------------------------------------------------
// FMA-only exp: e^x = 2^n * exp(f), f = x - n*ln2, |f| <= 0.347.
// deg-5 Taylor, rel err ~2.4e-6. No MUFU.
// ---------------------------------------------------------------------------
__device__ __forceinline__ float fexp(float x) {
    float z  = fmaf(x, 1.4426950408889634f, 12582912.0f);  // round(x*log2e) in mantissa
    int   iz = __float_as_int(z);
    float n  = z - 12582912.0f;
    float f  = fmaf(n, -0.6931471805599453f, x);
    float p  = 8.3333333e-3f;
    p = fmaf(p, f, 4.1666667e-2f);
    p = fmaf(p, f, 1.6666667e-1f);
    p = fmaf(p, f, 5.0e-1f);
    p = fmaf(p, f, 1.0f);
    p = fmaf(p, f, 1.0f);
    return __int_as_float(__float_as_int(p) + (iz << 23));  // * 2^n
}

// ---------------------------------------------------------------------------
// Kernel 1: QKV projection, register-tiled SGEMM.
// Block tile: 64 rows x 96 cols, 96 threads, thread tile 8x8.
// x and w both stored channel-major in smem with a k-rotation swizzle
// (identical for both arrays, so slot s pairs the same channel).
// grid = (576, 2): y selects the 96-col half of the 192 outputs.
// ---------------------------------------------------------------------------
#define XPAD 68    /* mod4==0 (16B align), mod32==4 (write spread) */
#define WPAD 100
__global__ __launch_bounds__(96) void qkv_kernel(const float* __restrict__ x,
                                                 const float* __restrict__ w,
                                                 const float* __restrict__ b) {
    __shared__ float xT[64*XPAD];   // [ch_slot][row]
    __shared__ float wT[64*WPAD];   // [ch_slot][col]
    int tid = threadIdx.x;
    int row0 = blockIdx.x * 64;
    int chunk = blockIdx.y * 96;    // output-column chunk

    // load + transpose x (64 rows x 64 ch), swizzled channel slots
    const float4* x4 = (const float4*)(x + (size_t)row0*64);
    for (int idx = tid; idx < 64*16; idx += 96) {
        int r = idx >> 4, cq = idx & 15;
        float4 v = x4[idx];
        float vv[4] = {v.x, v.y, v.z, v.w};
        #pragma unroll
        for (int k = 0; k < 4; k++) {
            int s = cq*4 + ((k + cq) & 3);
            xT[s*XPAD + r] = vv[k];
        }
    }
    // load + transpose w rows [chunk, chunk+96)
    const float4* w4 = (const float4*)(w + (size_t)chunk*64);
    for (int idx = tid; idx < 96*16; idx += 96) {
        int o = idx >> 4, cq = idx & 15;
        float4 v = w4[idx];
        float vv[4] = {v.x, v.y, v.z, v.w};
        #pragma unroll
        for (int k = 0; k < 4; k++) {
            int s = cq*4 + ((k + cq) & 3);
            wT[s*WPAD + o] = vv[k];
        }
    }
    __syncthreads();

    int cx = tid % 12, ry = tid / 12;     // 12 col-groups x 8 row-groups
    int r0 = ry*8, c0 = cx*8;

    float acc[8][8];
    #pragma unroll
    for (int i = 0; i < 8; i++)
        #pragma unroll
        for (int j = 0; j < 8; j++) acc[i][j] = 0.f;

    #pragma unroll 4
    for (int s = 0; s < 64; s++) {
        float4 xa = *(const float4*)&xT[s*XPAD + r0];
        float4 xb = *(const float4*)&xT[s*XPAD + r0 + 4];
        float4 wa = *(const float4*)&wT[s*WPAD + c0];
        float4 wb = *(const float4*)&wT[s*WPAD + c0 + 4];
        float xr[8] = {xa.x,xa.y,xa.z,xa.w, xb.x,xb.y,xb.z,xb.w};
        float wc[8] = {wa.x,wa.y,wa.z,wa.w, wb.x,wb.y,wb.z,wb.w};
        #pragma unroll
        for (int i = 0; i < 8; i++)
            #pragma unroll
            for (int j = 0; j < 8; j++)
                acc[i][j] = fmaf(xr[i], wc[j], acc[i][j]);
    }

    // epilogue
    int oc = chunk + c0;                       // absolute output column
    float bias[8];
    *(float4*)&bias[0] = __ldg((const float4*)(b + oc));
    *(float4*)&bias[4] = __ldg((const float4*)(b + oc + 4));
    float scale = (oc < 64) ? QSCALE : 1.f;
    float* dstbase = (oc < 64) ? g_Q : (oc < 128 ? g_K : g_V);
    int cc0 = oc & 63;
    #pragma unroll
    for (int i = 0; i < 8; i++) {
        size_t rb = (size_t)(row0 + r0 + i)*64 + cc0;
        float4 o0, o1;
        o0.x = (acc[i][0]+bias[0])*scale; o0.y = (acc[i][1]+bias[1])*scale;
        o0.z = (acc[i][2]+bias[2])*scale; o0.w = (acc[i][3]+bias[3])*scale;
        o1.x = (acc[i][4]+bias[4])*scale; o1.y = (acc[i][5]+bias[5])*scale;
        o1.z = (acc[i][6]+bias[6])*scale; o1.w = (acc[i][7]+bias[7])*scale;
        *(float4*)&dstbase[rb]     = o0;
        *(float4*)&dstbase[rb + 4] = o1;
    }
}

// ---------------------------------------------------------------------------
// Kernel 2: neighborhood attention (4 queries/thread, streaming softmax,
// no max subtraction, FMA-only exp) fused with proj + LayerNorm.
// Block = 192 threads = 24 qgroups (4 adjacent j) x 8 heads = 96 pixels
// (2 image rows). grid = 384.
// smem: pws 19456B | union{ rpb 5408B ; xout 96*68*4 = 26112B } -> 45568B
// ---------------------------------------------------------------------------
__global__ __launch_bounds__(192) void attn_proj_kernel(const float* __restrict__ rpb,
                                                        const float* __restrict__ pw,
                                                        const float* __restrict__ pb,
                                                        const float* __restrict__ lng,
                                                        const float* __restrict__ lnb,
                                                        float* __restrict__ out) {
    __shared__ float sbuf[4864 + 96*68];      // 19456B + 26112B
    float* pws   = sbuf;                       // [col][ch] padded 76
    float* xout  = sbuf + 4864;                // [96][68]
    float* rpb_s = sbuf + 4864;                // aliases xout (phase-disjoint)

    int tid = threadIdx.x;

    // stage proj weights (padded 76 floats/row) and rpb
    const float4* pw4 = (const float4*)pw;
    for (int idx = tid; idx < 1024; idx += 192) {
        int r = idx >> 4, c4 = idx & 15;
        ((float4*)(pws + r*76))[c4] = pw4[idx];
    }
    for (int idx = tid; idx < 8*169; idx += 192) rpb_s[idx] = rpb[idx];
    __syncthreads();

    int head = tid & 7, qg = tid >> 3;
    int blk = blockIdx.x;
    int bt = blk / 24, i0 = (blk % 24) * 2;
    int iofs = qg / 12, jg = qg % 12;
    int i = i0 + iofs, j0 = jg * 4;
    int si = min(max(i - 3, 0), HH - 7);
    int sj[4];
    #pragma unroll
    for (int q = 0; q < 4; q++) sj[q] = min(max(j0 + q - 3, 0), WW - 7);
    int cmin = sj[0];
    int ncols = sj[3] + 7 - cmin;   // 7..10

    const float4* Q4 = (const float4*)g_Q;
    const float4* K4 = (const float4*)g_K;
    const float4* V4 = (const float4*)g_V;

    float4 qa[4], qb[4];
    #pragma unroll
    for (int q = 0; q < 4; q++) {
        int qp = (bt*2304 + i*48 + j0 + q)*16 + head*2;
        qa[q] = Q4[qp]; qb[q] = Q4[qp+1];
    }

    float4 oa[4], ob[4];
    float l[4];
    #pragma unroll
    for (int q = 0; q < 4; q++) {
        oa[q] = make_float4(0.f,0.f,0.f,0.f);
        ob[q] = make_float4(0.f,0.f,0.f,0.f);
        l[q] = 0.f;
    }

    const float* hb = rpb_s + head*169;
    #pragma unroll
    for (int pr = 0; pr < 7; pr++) {
        int gi = si + pr;
        const float* brow = hb + (gi - i + 6)*13 + 6 - j0;  // index with [ci - q]
        int abase = (bt*2304 + gi*48)*16 + head*2;
        for (int cc = 0; cc < ncols; cc++) {
            int ci = cmin + cc;
            int a = abase + ci*16;
            float4 ka = K4[a], kb = K4[a+1];
            float4 va = V4[a], vb = V4[a+1];
            #pragma unroll
            for (int q = 0; q < 4; q++) {
                if ((unsigned)(ci - sj[q]) < 7u) {
                    float s = qa[q].x*ka.x + qa[q].y*ka.y + qa[q].z*ka.z + qa[q].w*ka.w
                            + qb[q].x*kb.x + qb[q].y*kb.y + qb[q].z*kb.z + qb[q].w*kb.w
                            + brow[ci - q];
                    float e = fexp(s);
                    l[q] += e;
                    oa[q].x = fmaf(e, va.x, oa[q].x); oa[q].y = fmaf(e, va.y, oa[q].y);
                    oa[q].z = fmaf(e, va.z, oa[q].z); oa[q].w = fmaf(e, va.w, oa[q].w);
                    ob[q].x = fmaf(e, vb.x, ob[q].x); ob[q].y = fmaf(e, vb.y, ob[q].y);
                    ob[q].z = fmaf(e, vb.z, ob[q].z); ob[q].w = fmaf(e, vb.w, ob[q].w);
                }
            }
        }
    }

    __syncthreads();   // all rpb_s reads complete before xout overwrites it

    int lp = qg*4;
    #pragma unroll
    for (int q = 0; q < 4; q++) {
        float inv = 1.f / l[q];
        oa[q].x *= inv; oa[q].y *= inv; oa[q].z *= inv; oa[q].w *= inv;
        ob[q].x *= inv; ob[q].y *= inv; ob[q].z *= inv; ob[q].w *= inv;
        *(float4*)&xout[(lp+q)*68 + head*8]     = oa[q];
        *(float4*)&xout[(lp+q)*68 + head*8 + 4] = ob[q];
    }
    __syncthreads();

    // ---- proj + LayerNorm: 6 warps x 16 rows; lane = channels {lane, lane+32}
    int warp = tid >> 5, lane = tid & 31;
    int c0 = lane, c1 = lane + 32;
    const float4* w0p = (const float4*)(pws + c0*76);
    const float4* w1p = (const float4*)(pws + c1*76);
    float pb0 = __ldg(&pb[c0]),  pb1 = __ldg(&pb[c1]);
    float g0  = __ldg(&lng[c0]), g1  = __ldg(&lng[c1]);
    float bb0 = __ldg(&lnb[c0]), bb1 = __ldg(&lnb[c1]);
    int blockpix0 = bt*2304 + i0*48;

    for (int rr = 0; rr < 16; rr++) {
        int lrow = warp*16 + rr;
        const float4* xr = (const float4*)(xout + lrow*68);
        float y0 = 0.f, y1 = 0.f;
        #pragma unroll
        for (int cc = 0; cc < 16; cc++) {
            float4 xv = xr[cc];
            float4 w0 = w0p[cc];
            float4 w1 = w1p[cc];
            y0 += xv.x*w0.x + xv.y*w0.y + xv.z*w0.z + xv.w*w0.w;
            y1 += xv.x*w1.x + xv.y*w1.y + xv.z*w1.z + xv.w*w1.w;
        }
        y0 += pb0; y1 += pb1;

        float s  = y0 + y1;
        float sq = y0*y0 + y1*y1;
        #pragma unroll
        for (int off = 16; off; off >>= 1) {
            s  += __shfl_xor_sync(0xffffffffu, s,  off);
            sq += __shfl_xor_sync(0xffffffffu, sq, off);
        }
        float mu  = s * (1.f/64.f);
        float var = sq * (1.f/64.f) - mu*mu;
        float rs  = rsqrtf(var + 1e-5f);

        size_t ob_idx = (size_t)(blockpix0 + lrow)*64;
        out[ob_idx + c0] = (y0 - mu)*rs*g0 + bb0;
        out[ob_idx + c1] = (y1 - mu)*rs*g1 + bb1;
    }
}

// ---------------------------------------------------------------------------
extern "C" void kernel_launch(void* const* d_in, const int* in_sizes, int n_in,
                              void* d_out, int out_size) {
    const float* q      = (const float*)d_in[0];
    const float* qkv_w  = (const float*)d_in[1];
    const float* qkv_b  = (const float*)d_in[2];
    const float* proj_w = (const float*)d_in[3];
    const float* proj_b = (const float*)d_in[4];
    const float* rpb    = (const float*)d_in[5];
    const float* ln_g   = (const float*)d_in[6];
    const float* ln_b   = (const float*)d_in[7];

    qkv_kernel<<<dim3(NPIX/64, 2), 96>>>(q, qkv_w, qkv_b);
    attn_proj_kernel<<<384, 192>>>(rpb, proj_w, proj_b, ln_g, ln_b, (float*)d_out);
}

// round 7
// speedup vs baseline: 2.1248x; 1.3218x over previous
#include <cuda_runtime.h>

#define BT 16
#define HH 48
#define WW 48
#define NPIX (BT*HH*WW)   /* 36864 */
#define QSCALE 0.35355339059327373f

// Scratch (static device allocations are allowed)
__device__ float g_Q[NPIX*64];
__device__ float g_K[NPIX*64];
__device__ float g_V[NPIX*64];

// ---------------------------------------------------------------------------
// FMA-only exp (no MUFU), rel err ~2.4e-6
// ---------------------------------------------------------------------------
__device__ __forceinline__ float fexp(float x) {
    float z  = fmaf(x, 1.4426950408889634f, 12582912.0f);
    int   iz = __float_as_int(z);
    float n  = z - 12582912.0f;
    float f  = fmaf(n, -0.6931471805599453f, x);
    float p  = 8.3333333e-3f;
    p = fmaf(p, f, 4.1666667e-2f);
    p = fmaf(p, f, 1.6666667e-1f);
    p = fmaf(p, f, 5.0e-1f);
    p = fmaf(p, f, 1.0f);
    p = fmaf(p, f, 1.0f);
    return __int_as_float(__float_as_int(p) + (iz << 23));
}

// ---------------------------------------------------------------------------
// Kernel 1: QKV projection, register-tiled SGEMM (unchanged from R5).
// ---------------------------------------------------------------------------
#define XPAD 68
#define WPAD 100
__global__ __launch_bounds__(96) void qkv_kernel(const float* __restrict__ x,
                                                 const float* __restrict__ w,
                                                 const float* __restrict__ b) {
    __shared__ float xT[64*XPAD];
    __shared__ float wT[64*WPAD];
    int tid = threadIdx.x;
    int row0 = blockIdx.x * 64;
    int chunk = blockIdx.y * 96;

    const float4* x4 = (const float4*)(x + (size_t)row0*64);
    for (int idx = tid; idx < 64*16; idx += 96) {
        int r = idx >> 4, cq = idx & 15;
        float4 v = x4[idx];
        float vv[4] = {v.x, v.y, v.z, v.w};
        #pragma unroll
        for (int k = 0; k < 4; k++) {
            int s = cq*4 + ((k + cq) & 3);
            xT[s*XPAD + r] = vv[k];
        }
    }
    const float4* w4 = (const float4*)(w + (size_t)chunk*64);
    for (int idx = tid; idx < 96*16; idx += 96) {
        int o = idx >> 4, cq = idx & 15;
        float4 v = w4[idx];
        float vv[4] = {v.x, v.y, v.z, v.w};
        #pragma unroll
        for (int k = 0; k < 4; k++) {
            int s = cq*4 + ((k + cq) & 3);
            wT[s*WPAD + o] = vv[k];
        }
    }
    __syncthreads();

    int cx = tid % 12, ry = tid / 12;
    int r0 = ry*8, c0 = cx*8;

    float acc[8][8];
    #pragma unroll
    for (int i = 0; i < 8; i++)
        #pragma unroll
        for (int j = 0; j < 8; j++) acc[i][j] = 0.f;

    #pragma unroll 4
    for (int s = 0; s < 64; s++) {
        float4 xa = *(const float4*)&xT[s*XPAD + r0];
        float4 xb = *(const float4*)&xT[s*XPAD + r0 + 4];
        float4 wa = *(const float4*)&wT[s*WPAD + c0];
        float4 wb = *(const float4*)&wT[s*WPAD + c0 + 4];
        float xr[8] = {xa.x,xa.y,xa.z,xa.w, xb.x,xb.y,xb.z,xb.w};
        float wc[8] = {wa.x,wa.y,wa.z,wa.w, wb.x,wb.y,wb.z,wb.w};
        #pragma unroll
        for (int i = 0; i < 8; i++)
            #pragma unroll
            for (int j = 0; j < 8; j++)
                acc[i][j] = fmaf(xr[i], wc[j], acc[i][j]);
    }

    int oc = chunk + c0;
    float bias[8];
    *(float4*)&bias[0] = __ldg((const float4*)(b + oc));
    *(float4*)&bias[4] = __ldg((const float4*)(b + oc + 4));
    float scale = (oc < 64) ? QSCALE : 1.f;
    float* dstbase = (oc < 64) ? g_Q : (oc < 128 ? g_K : g_V);
    int cc0 = oc & 63;
    #pragma unroll
    for (int i = 0; i < 8; i++) {
        size_t rb = (size_t)(row0 + r0 + i)*64 + cc0;
        float4 o0, o1;
        o0.x = (acc[i][0]+bias[0])*scale; o0.y = (acc[i][1]+bias[1])*scale;
        o0.z = (acc[i][2]+bias[2])*scale; o0.w = (acc[i][3]+bias[3])*scale;
        o1.x = (acc[i][4]+bias[4])*scale; o1.y = (acc[i][5]+bias[5])*scale;
        o1.z = (acc[i][6]+bias[6])*scale; o1.w = (acc[i][7]+bias[7])*scale;
        *(float4*)&dstbase[rb]     = o0;
        *(float4*)&dstbase[rb + 4] = o1;
    }
}

// ---------------------------------------------------------------------------
// Kernel 2: attention (smem-staged K/V) + proj + LayerNorm.
// Block = 2 image rows (96 px) x 8 heads; 384 threads, thread = (j, head),
// 2 vertically-adjacent queries per thread sharing every K/V read.
// K/V staged per-head with stride 3076 floats -> conflict-free LDS.128.
// Proj phase aliases xout over K region and padded weights over V region.
// ---------------------------------------------------------------------------
#define HSTRIDE 3076                 /* per-head tile stride (floats): 4h banks */
#define KV_FLOATS (8*HSTRIDE)        /* 24608 */
#define RPB_OFF   (2*KV_FLOATS)      /* 49216 */
#define SMEM_FLOATS (RPB_OFF + 8*169)/* 50568 -> 202272 bytes */

extern __shared__ float sdyn[];

__global__ __launch_bounds__(384) void attn_proj_kernel(const float* __restrict__ rpb,
                                                        const float* __restrict__ pw,
                                                        const float* __restrict__ pb,
                                                        const float* __restrict__ lng,
                                                        const float* __restrict__ lnb,
                                                        float* __restrict__ out) {
    float* Ks    = sdyn;
    float* Vs    = sdyn + KV_FLOATS;
    float* rpb_s = sdyn + RPB_OFF;
    float* xout  = Ks;               // alias after attention phase  [96][64]
    float* pws   = Vs;               // alias after attention phase  [64][68]

    int tid = threadIdx.x;
    int blk = blockIdx.x;
    int bt = blk / 24, i0 = (blk % 24) * 2;
    int strip = bt * 2304;

    // ---- stage rpb
    for (int idx = tid; idx < 8*169; idx += 384) rpb_s[idx] = rpb[idx];

    // ---- stage K/V tile: rows r0..r0+7 (clamped), scatter to per-head layout
    int r0 = min(max(i0 - 3, 0), 41);
    {
        const float4* Kg4 = (const float4*)g_K;
        const float4* Vg4 = (const float4*)g_V;
        for (int idx = tid; idx < 8*768; idx += 384) {
            int r = idx / 768;
            int rem = idx - r*768;
            int c = rem >> 4, q = rem & 15;
            int gi = min(r0 + r, 47);
            int gsrc = (strip + gi*48 + c)*16 + q;
            int head = q >> 1, part = q & 1;
            int dst = head*HSTRIDE + r*384 + c*8 + part*4;
            *(float4*)(Ks + dst) = Kg4[gsrc];
            *(float4*)(Vs + dst) = Vg4[gsrc];
        }
    }
    __syncthreads();

    int j = tid >> 3, head = tid & 7;
    int sj  = min(max(j - 3, 0), 41);
    int si0 = r0;                          // clamp(i0-3)
    int si1 = min(max(i0 - 2, 0), 41);
    int d1  = si1 - si0;                   // 0 or 1

    const float4* Q4 = (const float4*)g_Q;
    int qp0 = (strip + i0*48 + j)*16 + head*2;
    float4 q0a = Q4[qp0],     q0b = Q4[qp0+1];
    float4 q1a = Q4[qp0+768], q1b = Q4[qp0+769];

    float4 o0a = make_float4(0,0,0,0), o0b = make_float4(0,0,0,0);
    float4 o1a = make_float4(0,0,0,0), o1b = make_float4(0,0,0,0);
    float l0 = 0.f, l1 = 0.f;

    const float* hb = rpb_s + head*169;
    int bcol = sj - j + 6;

    #pragma unroll 2
    for (int r = 0; r < 8; r++) {
        bool a0 = (r < 7);
        bool a1 = ((unsigned)(r - d1) < 7u);
        const float* br0 = hb + (r0 + r - i0 + 6)*13 + bcol;
        const float* br1 = br0 - 13;
        const float* kp = Ks + head*HSTRIDE + r*384 + sj*8;
        const float* vp = Vs + head*HSTRIDE + r*384 + sj*8;
        #pragma unroll
        for (int c = 0; c < 7; c++) {
            float4 ka = *(const float4*)(kp + c*8);
            float4 kb = *(const float4*)(kp + c*8 + 4);
            float4 va = *(const float4*)(vp + c*8);
            float4 vb = *(const float4*)(vp + c*8 + 4);
            if (a0) {
                float s = q0a.x*ka.x + q0a.y*ka.y + q0a.z*ka.z + q0a.w*ka.w
                        + q0b.x*kb.x + q0b.y*kb.y + q0b.z*kb.z + q0b.w*kb.w
                        + br0[c];
                float e = fexp(s);
                l0 += e;
                o0a.x = fmaf(e, va.x, o0a.x); o0a.y = fmaf(e, va.y, o0a.y);
                o0a.z = fmaf(e, va.z, o0a.z); o0a.w = fmaf(e, va.w, o0a.w);
                o0b.x = fmaf(e, vb.x, o0b.x); o0b.y = fmaf(e, vb.y, o0b.y);
                o0b.z = fmaf(e, vb.z, o0b.z); o0b.w = fmaf(e, vb.w, o0b.w);
            }
            if (a1) {
                float s = q1a.x*ka.x + q1a.y*ka.y + q1a.z*ka.z + q1a.w*ka.w
                        + q1b.x*kb.x + q1b.y*kb.y + q1b.z*kb.z + q1b.w*kb.w
                        + br1[c];
                float e = fexp(s);
                l1 += e;
                o1a.x = fmaf(e, va.x, o1a.x); o1a.y = fmaf(e, va.y, o1a.y);
                o1a.z = fmaf(e, va.z, o1a.z); o1a.w = fmaf(e, va.w, o1a.w);
                o1b.x = fmaf(e, vb.x, o1b.x); o1b.y = fmaf(e, vb.y, o1b.y);
                o1b.z = fmaf(e, vb.z, o1b.z); o1b.w = fmaf(e, vb.w, o1b.w);
            }
        }
    }
    __syncthreads();   // all Ks/Vs reads done; safe to alias

    // ---- write attention outputs to xout [96][64]
    {
        float inv0 = 1.f / l0, inv1 = 1.f / l1;
        o0a.x*=inv0; o0a.y*=inv0; o0a.z*=inv0; o0a.w*=inv0;
        o0b.x*=inv0; o0b.y*=inv0; o0b.z*=inv0; o0b.w*=inv0;
        o1a.x*=inv1; o1a.y*=inv1; o1a.z*=inv1; o1a.w*=inv1;
        o1b.x*=inv1; o1b.y*=inv1; o1b.z*=inv1; o1b.w*=inv1;
        *(float4*)(xout + j*64 + head*8)          = o0a;
        *(float4*)(xout + j*64 + head*8 + 4)      = o0b;
        *(float4*)(xout + (48+j)*64 + head*8)     = o1a;
        *(float4*)(xout + (48+j)*64 + head*8 + 4) = o1b;
    }
    // ---- stage proj weights [64][68] (padded, conflict-free)
    {
        const float4* pw4 = (const float4*)pw;
        for (int idx = tid; idx < 1024; idx += 384) {
            int c = idx >> 4, qq = idx & 15;
            *(float4*)(pws + c*68 + qq*4) = pw4[idx];
        }
    }
    __syncthreads();

    // ---- proj + LayerNorm: 12 warps x 8 rows
    int warp = tid >> 5, lane = tid & 31;
    int c0 = lane, c1 = lane + 32;
    const float4* w0p = (const float4*)(pws + c0*68);
    const float4* w1p = (const float4*)(pws + c1*68);
    float pb0 = __ldg(&pb[c0]),  pb1 = __ldg(&pb[c1]);
    float g0  = __ldg(&lng[c0]), g1  = __ldg(&lng[c1]);
    float bb0 = __ldg(&lnb[c0]), bb1 = __ldg(&lnb[c1]);

    #pragma unroll 2
    for (int rr = 0; rr < 8; rr++) {
        int lr = warp*8 + rr;
        const float4* xr = (const float4*)(xout + lr*64);
        float y0 = 0.f, y1 = 0.f;
        #pragma unroll
        for (int cc = 0; cc < 16; cc++) {
            float4 xv = xr[cc];
            float4 w0 = w0p[cc];
            float4 w1 = w1p[cc];
            y0 += xv.x*w0.x + xv.y*w0.y + xv.z*w0.z + xv.w*w0.w;
            y1 += xv.x*w1.x + xv.y*w1.y + xv.z*w1.z + xv.w*w1.w;
        }
        y0 += pb0; y1 += pb1;

        float s  = y0 + y1;
        float sq = y0*y0 + y1*y1;
        #pragma unroll
        for (int off = 16; off; off >>= 1) {
            s  += __shfl_xor_sync(0xffffffffu, s,  off);
            sq += __shfl_xor_sync(0xffffffffu, sq, off);
        }
        float mu  = s * (1.f/64.f);
        float var = sq * (1.f/64.f) - mu*mu;
        float rs  = rsqrtf(var + 1e-5f);

        int lrow = (lr >= 48);
        int pix = strip + (i0 + lrow)*48 + (lr - lrow*48);
        out[(size_t)pix*64 + c0] = (y0 - mu)*rs*g0 + bb0;
        out[(size_t)pix*64 + c1] = (y1 - mu)*rs*g1 + bb1;
    }
}

// ---------------------------------------------------------------------------
extern "C" void kernel_launch(void* const* d_in, const int* in_sizes, int n_in,
                              void* d_out, int out_size) {
    const float* q      = (const float*)d_in[0];
    const float* qkv_w  = (const float*)d_in[1];
    const float* qkv_b  = (const float*)d_in[2];
    const float* proj_w = (const float*)d_in[3];
    const float* proj_b = (const float*)d_in[4];
    const float* rpb    = (const float*)d_in[5];
    const float* ln_g   = (const float*)d_in[6];
    const float* ln_b   = (const float*)d_in[7];

    cudaFuncSetAttribute(attn_proj_kernel,
                         cudaFuncAttributeMaxDynamicSharedMemorySize,
                         SMEM_FLOATS * 4);

    qkv_kernel<<<dim3(NPIX/64, 2), 96>>>(q, qkv_w, qkv_b);
    attn_proj_kernel<<<384, 384, SMEM_FLOATS * 4>>>(rpb, proj_w, proj_b,
                                                    ln_g, ln_b, (float*)d_out);
}

// round 8
// speedup vs baseline: 2.1526x; 1.0131x over previous
#include <cuda_runtime.h>

#define BT 16
#define HH 48
#define WW 48
#define NPIX (BT*HH*WW)   /* 36864 */
#define QSCALE 0.35355339059327373f

// Scratch (static device allocations are allowed)
__device__ float g_Q[NPIX*64];
__device__ float g_K[NPIX*64];
__device__ float g_V[NPIX*64];

// ---------------------------------------------------------------------------
// FMA-only exp (no MUFU), rel err ~2.4e-6
// ---------------------------------------------------------------------------
__device__ __forceinline__ float fexp(float x) {
    float z  = fmaf(x, 1.4426950408889634f, 12582912.0f);
    int   iz = __float_as_int(z);
    float n  = z - 12582912.0f;
    float f  = fmaf(n, -0.6931471805599453f, x);
    float p  = 8.3333333e-3f;
    p = fmaf(p, f, 4.1666667e-2f);
    p = fmaf(p, f, 1.6666667e-1f);
    p = fmaf(p, f, 5.0e-1f);
    p = fmaf(p, f, 1.0f);
    p = fmaf(p, f, 1.0f);
    return __int_as_float(__float_as_int(p) + (iz << 23));
}

// ---------------------------------------------------------------------------
// Kernel 1: QKV projection, register-tiled SGEMM (unchanged).
// ---------------------------------------------------------------------------
#define XPAD 68
#define WPAD 100
__global__ __launch_bounds__(96) void qkv_kernel(const float* __restrict__ x,
                                                 const float* __restrict__ w,
                                                 const float* __restrict__ b) {
    __shared__ float xT[64*XPAD];
    __shared__ float wT[64*WPAD];
    int tid = threadIdx.x;
    int row0 = blockIdx.x * 64;
    int chunk = blockIdx.y * 96;

    const float4* x4 = (const float4*)(x + (size_t)row0*64);
    for (int idx = tid; idx < 64*16; idx += 96) {
        int r = idx >> 4, cq = idx & 15;
        float4 v = x4[idx];
        float vv[4] = {v.x, v.y, v.z, v.w};
        #pragma unroll
        for (int k = 0; k < 4; k++) {
            int s = cq*4 + ((k + cq) & 3);
            xT[s*XPAD + r] = vv[k];
        }
    }
    const float4* w4 = (const float4*)(w + (size_t)chunk*64);
    for (int idx = tid; idx < 96*16; idx += 96) {
        int o = idx >> 4, cq = idx & 15;
        float4 v = w4[idx];
        float vv[4] = {v.x, v.y, v.z, v.w};
        #pragma unroll
        for (int k = 0; k < 4; k++) {
            int s = cq*4 + ((k + cq) & 3);
            wT[s*WPAD + o] = vv[k];
        }
    }
    __syncthreads();

    int cx = tid % 12, ry = tid / 12;
    int r0 = ry*8, c0 = cx*8;

    float acc[8][8];
    #pragma unroll
    for (int i = 0; i < 8; i++)
        #pragma unroll
        for (int j = 0; j < 8; j++) acc[i][j] = 0.f;

    #pragma unroll 4
    for (int s = 0; s < 64; s++) {
        float4 xa = *(const float4*)&xT[s*XPAD + r0];
        float4 xb = *(const float4*)&xT[s*XPAD + r0 + 4];
        float4 wa = *(const float4*)&wT[s*WPAD + c0];
        float4 wb = *(const float4*)&wT[s*WPAD + c0 + 4];
        float xr[8] = {xa.x,xa.y,xa.z,xa.w, xb.x,xb.y,xb.z,xb.w};
        float wc[8] = {wa.x,wa.y,wa.z,wa.w, wb.x,wb.y,wb.z,wb.w};
        #pragma unroll
        for (int i = 0; i < 8; i++)
            #pragma unroll
            for (int j = 0; j < 8; j++)
                acc[i][j] = fmaf(xr[i], wc[j], acc[i][j]);
    }

    int oc = chunk + c0;
    float bias[8];
    *(float4*)&bias[0] = __ldg((const float4*)(b + oc));
    *(float4*)&bias[4] = __ldg((const float4*)(b + oc + 4));
    float scale = (oc < 64) ? QSCALE : 1.f;
    float* dstbase = (oc < 64) ? g_Q : (oc < 128 ? g_K : g_V);
    int cc0 = oc & 63;
    #pragma unroll
    for (int i = 0; i < 8; i++) {
        size_t rb = (size_t)(row0 + r0 + i)*64 + cc0;
        float4 o0, o1;
        o0.x = (acc[i][0]+bias[0])*scale; o0.y = (acc[i][1]+bias[1])*scale;
        o0.z = (acc[i][2]+bias[2])*scale; o0.w = (acc[i][3]+bias[3])*scale;
        o1.x = (acc[i][4]+bias[4])*scale; o1.y = (acc[i][5]+bias[5])*scale;
        o1.z = (acc[i][6]+bias[6])*scale; o1.w = (acc[i][7]+bias[7])*scale;
        *(float4*)&dstbase[rb]     = o0;
        *(float4*)&dstbase[rb + 4] = o1;
    }
}

// ---------------------------------------------------------------------------
// Kernel 2: attention (half-split threads) + proj + LayerNorm.
// Block = 768 threads: thread = (j, head, half). 2 vertical queries/thread.
// Each half computes a 4-channel partial dot; shfl_xor(8) combines.
// K/V smem: pixel-major, slot permutation (f*8+h) -> conflict-free LDS.128.
// Proj: warp = 4 rows, weights loaded once per 4 rows, x via broadcast LDS.
// ---------------------------------------------------------------------------
#define KV_FLOATS (8*48*64)          /* 24576 */
#define RPB_OFF   (2*KV_FLOATS)      /* 49152 */
#define SMEM_FLOATS (RPB_OFF + 8*169 + 64)

extern __shared__ float sdyn[];

__global__ __launch_bounds__(768) void attn_proj_kernel(const float* __restrict__ rpb,
                                                        const float* __restrict__ pw,
                                                        const float* __restrict__ pb,
                                                        const float* __restrict__ lng,
                                                        const float* __restrict__ lnb,
                                                        float* __restrict__ out) {
    float* Ks    = sdyn;
    float* Vs    = sdyn + KV_FLOATS;
    float* rpb_s = sdyn + RPB_OFF;
    float* xout  = Ks;               // alias after attention: [96][64]
    float* pws   = Vs;               // alias after attention: [64][68]

    int tid = threadIdx.x;
    int blk = blockIdx.x;
    int bt = blk / 24, i0 = (blk % 24) * 2;
    int strip = bt * 2304;

    for (int idx = tid; idx < 8*169; idx += 768) rpb_s[idx] = rpb[idx];

    // ---- stage K/V: 8 rows, slot-permuted layout (dst linear -> no STS conflicts)
    int r0 = min(max(i0 - 3, 0), 41);
    {
        const float4* Kg4 = (const float4*)g_K;
        const float4* Vg4 = (const float4*)g_V;
        int c = tid >> 4, s = tid & 15;
        int q = ((s & 7) << 1) | (s >> 3);       // src float4 for dst slot s
        int dstb = c*64 + s*4;
        int srcb = (strip + c)*16 + q;
        #pragma unroll
        for (int r = 0; r < 8; r++) {
            int gi = min(r0 + r, 47);
            int src = srcb + gi*768;             // (strip + gi*48 + c)*16 + q
            *(float4*)(Ks + r*3072 + dstb) = Kg4[src];
            *(float4*)(Vs + r*3072 + dstb) = Vg4[src];
        }
    }
    __syncthreads();

    // ---- attention
    int j = tid >> 4;
    int f = (tid >> 3) & 1;
    int h = tid & 7;
    int sj  = min(max(j - 3, 0), 41);
    int si1 = min(max(i0 - 2, 0), 41);
    int d1  = si1 - r0;                     // 0 or 1
    float m_r0 = (d1 == 0) ? 1.f : 0.f;     // q1 valid at r=0
    float m_r7 = 1.f - m_r0;                // q1 valid at r=7

    const float4* Q4 = (const float4*)g_Q;
    int qf4 = h*2 + f;                      // float4 index of this half's channels
    int p0  = strip + i0*48 + j;
    float4 q0 = Q4[p0*16 + qf4];
    float4 q1 = Q4[(p0 + 48)*16 + qf4];

    float o0x=0,o0y=0,o0z=0,o0w=0;
    float o1x=0,o1y=0,o1z=0,o1w=0;
    float l0=0.f, l1=0.f;

    int chof = (f*8 + h)*4;                 // smem slot offset
    const float* hb = rpb_s + h*169;
    int bcol = sj - j + 6;
    int bri0 = r0 - i0 + 6;

    #pragma unroll
    for (int r = 0; r < 8; r++) {
        float w0 = (r == 7) ? 0.f : 1.f;
        float w1 = (r == 0) ? m_r0 : ((r == 7) ? m_r7 : 1.f);
        const float* kp = Ks + r*3072 + sj*64 + chof;
        const float* vp = Vs + r*3072 + sj*64 + chof;
        const float* b0 = hb + (bri0 + r)*13 + bcol;
        const float* b1 = b0 - 13;
        #pragma unroll
        for (int c = 0; c < 7; c++) {
            float4 k4 = *(const float4*)(kp + c*64);
            float4 v4 = *(const float4*)(vp + c*64);
            float sp0 = q0.x*k4.x + q0.y*k4.y + q0.z*k4.z + q0.w*k4.w;
            float sp1 = q1.x*k4.x + q1.y*k4.y + q1.z*k4.z + q1.w*k4.w;
            float s0 = sp0 + __shfl_xor_sync(0xffffffffu, sp0, 8);
            float s1 = sp1 + __shfl_xor_sync(0xffffffffu, sp1, 8);
            float e0 = fexp(s0 + b0[c]) * w0;
            float e1 = fexp(s1 + b1[c]) * w1;
            l0 += e0; l1 += e1;
            o0x = fmaf(e0, v4.x, o0x); o0y = fmaf(e0, v4.y, o0y);
            o0z = fmaf(e0, v4.z, o0z); o0w = fmaf(e0, v4.w, o0w);
            o1x = fmaf(e1, v4.x, o1x); o1y = fmaf(e1, v4.y, o1y);
            o1z = fmaf(e1, v4.z, o1z); o1w = fmaf(e1, v4.w, o1w);
        }
    }
    __syncthreads();   // all Ks/Vs reads done; safe to alias

    // ---- write attention outputs to xout [96][64] (original channel order)
    {
        float inv0 = 1.f / l0, inv1 = 1.f / l1;
        float4 u0 = make_float4(o0x*inv0, o0y*inv0, o0z*inv0, o0w*inv0);
        float4 u1 = make_float4(o1x*inv1, o1y*inv1, o1z*inv1, o1w*inv1);
        int co = h*8 + f*4;
        *(float4*)(xout + j*64 + co)        = u0;
        *(float4*)(xout + (48 + j)*64 + co) = u1;
    }
    // ---- stage proj weights [64][68]
    {
        const float4* pw4 = (const float4*)pw;
        for (int idx = tid; idx < 1024; idx += 768) {
            int cch = idx >> 4, qq = idx & 15;
            *(float4*)(pws + cch*68 + qq*4) = pw4[idx];
        }
    }
    __syncthreads();

    // ---- proj + LayerNorm: warp = 4 rows; lane = channels {lane, lane+32}
    int warp = tid >> 5, lane = tid & 31;
    int c0 = lane, c1 = lane + 32;
    const float4* w0p = (const float4*)(pws + c0*68);
    const float4* w1p = (const float4*)(pws + c1*68);
    float pb0 = __ldg(&pb[c0]),  pb1 = __ldg(&pb[c1]);
    float g0  = __ldg(&lng[c0]), g1  = __ldg(&lng[c1]);
    float bb0 = __ldg(&lnb[c0]), bb1 = __ldg(&lnb[c1]);
    int row0l = warp * 4;

    float y[4][2];
    #pragma unroll
    for (int rr = 0; rr < 4; rr++) { y[rr][0] = 0.f; y[rr][1] = 0.f; }

    #pragma unroll
    for (int cc = 0; cc < 16; cc++) {
        float4 wv0 = w0p[cc];
        float4 wv1 = w1p[cc];
        #pragma unroll
        for (int rr = 0; rr < 4; rr++) {
            float4 xv = *(const float4*)(xout + (row0l + rr)*64 + cc*4);
            y[rr][0] += xv.x*wv0.x + xv.y*wv0.y + xv.z*wv0.z + xv.w*wv0.w;
            y[rr][1] += xv.x*wv1.x + xv.y*wv1.y + xv.z*wv1.z + xv.w*wv1.w;
        }
    }

    #pragma unroll
    for (int rr = 0; rr < 4; rr++) {
        float y0 = y[rr][0] + pb0;
        float y1 = y[rr][1] + pb1;
        float s  = y0 + y1;
        float sq = y0*y0 + y1*y1;
        #pragma unroll
        for (int off = 16; off; off >>= 1) {
            s  += __shfl_xor_sync(0xffffffffu, s,  off);
            sq += __shfl_xor_sync(0xffffffffu, sq, off);
        }
        float mu  = s * (1.f/64.f);
        float var = sq * (1.f/64.f) - mu*mu;
        float rs  = rsqrtf(var + 1e-5f);

        int lr = row0l + rr;
        int irow = (lr >= 48);
        int pix = strip + (i0 + irow)*48 + (lr - irow*48);
        out[(size_t)pix*64 + c0] = (y0 - mu)*rs*g0 + bb0;
        out[(size_t)pix*64 + c1] = (y1 - mu)*rs*g1 + bb1;
    }
}

// ---------------------------------------------------------------------------
extern "C" void kernel_launch(void* const* d_in, const int* in_sizes, int n_in,
                              void* d_out, int out_size) {
    const float* q      = (const float*)d_in[0];
    const float* qkv_w  = (const float*)d_in[1];
    const float* qkv_b  = (const float*)d_in[2];
    const float* proj_w = (const float*)d_in[3];
    const float* proj_b = (const float*)d_in[4];
    const float* rpb    = (const float*)d_in[5];
    const float* ln_g   = (const float*)d_in[6];
    const float* ln_b   = (const float*)d_in[7];

    cudaFuncSetAttribute(attn_proj_kernel,
                         cudaFuncAttributeMaxDynamicSharedMemorySize,
                         SMEM_FLOATS * 4);

    qkv_kernel<<<dim3(NPIX/64, 2), 96>>>(q, qkv_w, qkv_b);
    attn_proj_kernel<<<384, 768, SMEM_FLOATS * 4>>>(rpb, proj_w, proj_b,
                                                    ln_g, ln_b, (float*)d_out);
}

// round 10
// speedup vs baseline: 2.3031x; 1.0699x over previous
#include <cuda_runtime.h>

#define BT 16
#define HH 48
#define WW 48
#define NPIX (BT*HH*WW)   /* 36864 */
#define QSCALE 0.35355339059327373f

// Scratch (static device allocations are allowed)
__device__ float g_Q[NPIX*64];
__device__ float g_K[NPIX*64];
__device__ float g_V[NPIX*64];

extern __shared__ float sdyn[];

// ---------------------------------------------------------------------------
// FMA-only exp (no MUFU), rel err ~2.4e-6
// ---------------------------------------------------------------------------
__device__ __forceinline__ float fexp(float x) {
    float z  = fmaf(x, 1.4426950408889634f, 12582912.0f);
    int   iz = __float_as_int(z);
    float n  = z - 12582912.0f;
    float f  = fmaf(n, -0.6931471805599453f, x);
    float p  = 8.3333333e-3f;
    p = fmaf(p, f, 4.1666667e-2f);
    p = fmaf(p, f, 1.6666667e-1f);
    p = fmaf(p, f, 5.0e-1f);
    p = fmaf(p, f, 1.0f);
    p = fmaf(p, f, 1.0f);
    return __int_as_float(__float_as_int(p) + (iz << 23));
}

// ---------------------------------------------------------------------------
// Kernel 1: QKV projection, register-tiled SGEMM.
// Block tile: 128 rows x 96 cols, 192 threads, thread tile 8x8.
// Dynamic smem: xT 64x132, wT 64x100.
// ---------------------------------------------------------------------------
#define XPAD 132
#define WPAD 100
#define QKV_SMEM ((64*XPAD + 64*WPAD)*4)

__global__ __launch_bounds__(192) void qkv_kernel(const float* __restrict__ x,
                                                  const float* __restrict__ w,
                                                  const float* __restrict__ b) {
    float* xT = sdyn;              // [ch_slot][row 128]
    float* wT = sdyn + 64*XPAD;    // [ch_slot][col 96]
    int tid = threadIdx.x;
    int row0 = blockIdx.x * 128;
    int chunk = blockIdx.y * 96;

    const float4* x4 = (const float4*)(x + (size_t)row0*64);
    for (int idx = tid; idx < 128*16; idx += 192) {
        int r = idx >> 4, cq = idx & 15;
        float4 v = x4[idx];
        float vv[4] = {v.x, v.y, v.z, v.w};
        #pragma unroll
        for (int k = 0; k < 4; k++) {
            int s = cq*4 + ((k + cq) & 3);
            xT[s*XPAD + r] = vv[k];
        }
    }
    const float4* w4 = (const float4*)(w + (size_t)chunk*64);
    for (int idx = tid; idx < 96*16; idx += 192) {
        int o = idx >> 4, cq = idx & 15;
        float4 v = w4[idx];
        float vv[4] = {v.x, v.y, v.z, v.w};
        #pragma unroll
        for (int k = 0; k < 4; k++) {
            int s = cq*4 + ((k + cq) & 3);
            wT[s*WPAD + o] = vv[k];
        }
    }
    __syncthreads();

    int cx = tid % 12, ry = tid / 12;     // 12 col-groups x 16 row-groups
    int r0 = ry*8, c0 = cx*8;

    float acc[8][8];
    #pragma unroll
    for (int i = 0; i < 8; i++)
        #pragma unroll
        for (int j = 0; j < 8; j++) acc[i][j] = 0.f;

    #pragma unroll 4
    for (int s = 0; s < 64; s++) {
        float4 xa = *(const float4*)&xT[s*XPAD + r0];
        float4 xb = *(const float4*)&xT[s*XPAD + r0 + 4];
        float4 wa = *(const float4*)&wT[s*WPAD + c0];
        float4 wb = *(const float4*)&wT[s*WPAD + c0 + 4];
        float xr[8] = {xa.x,xa.y,xa.z,xa.w, xb.x,xb.y,xb.z,xb.w};
        float wc[8] = {wa.x,wa.y,wa.z,wa.w, wb.x,wb.y,wb.z,wb.w};
        #pragma unroll
        for (int i = 0; i < 8; i++)
            #pragma unroll
            for (int j = 0; j < 8; j++)
                acc[i][j] = fmaf(xr[i], wc[j], acc[i][j]);
    }

    int oc = chunk + c0;
    float bias[8];
    *(float4*)&bias[0] = __ldg((const float4*)(b + oc));
    *(float4*)&bias[4] = __ldg((const float4*)(b + oc + 4));
    float scale = (oc < 64) ? QSCALE : 1.f;
    float* dstbase = (oc < 64) ? g_Q : (oc < 128 ? g_K : g_V);
    int cc0 = oc & 63;
    #pragma unroll
    for (int i = 0; i < 8; i++) {
        size_t rb = (size_t)(row0 + r0 + i)*64 + cc0;
        float4 o0, o1;
        o0.x = (acc[i][0]+bias[0])*scale; o0.y = (acc[i][1]+bias[1])*scale;
        o0.z = (acc[i][2]+bias[2])*scale; o0.w = (acc[i][3]+bias[3])*scale;
        o1.x = (acc[i][4]+bias[4])*scale; o1.y = (acc[i][5]+bias[5])*scale;
        o1.z = (acc[i][6]+bias[6])*scale; o1.w = (acc[i][7]+bias[7])*scale;
        *(float4*)&dstbase[rb]     = o0;
        *(float4*)&dstbase[rb + 4] = o1;
    }
}

// ---------------------------------------------------------------------------
// Kernel 2: attention (half-split, query-ownership softmax) + proj + LN.
// Block = 768 threads: thread = (j, head, half f). Thread OWNS query row
// i0+f (computes its exp); partner (xor 8) owns the other row. Per score:
// 1 shfl (partial exchange) + 1 fexp + 1 shfl (e exchange).
// ---------------------------------------------------------------------------
#define KV_FLOATS (8*48*64)          /* 24576 */
#define RPB_OFF   (2*KV_FLOATS)      /* 49152 */
#define ATTN_SMEM ((RPB_OFF + 8*169 + 64)*4)

__global__ __launch_bounds__(768) void attn_proj_kernel(const float* __restrict__ rpb,
                                                        const float* __restrict__ pw,
                                                        const float* __restrict__ pb,
                                                        const float* __restrict__ lng,
                                                        const float* __restrict__ lnb,
                                                        float* __restrict__ out) {
    float* Ks    = sdyn;
    float* Vs    = sdyn + KV_FLOATS;
    float* rpb_s = sdyn + RPB_OFF;
    float* xout  = Ks;               // alias after attention: [96][64]
    float* pws   = Vs;               // alias after attention: [64][68]

    int tid = threadIdx.x;
    int blk = blockIdx.x;
    int bt = blk / 24, i0 = (blk % 24) * 2;
    int strip = bt * 2304;

    for (int idx = tid; idx < 8*169; idx += 768) rpb_s[idx] = rpb[idx];

    // ---- stage K/V: 8 rows, slot-permuted layout
    int r0 = min(max(i0 - 3, 0), 41);
    {
        const float4* Kg4 = (const float4*)g_K;
        const float4* Vg4 = (const float4*)g_V;
        int c = tid >> 4, s = tid & 15;
        int q = ((s & 7) << 1) | (s >> 3);       // src float4 for dst slot s
        int dstb = c*64 + s*4;
        int srcb = (strip + c)*16 + q;
        #pragma unroll
        for (int r = 0; r < 8; r++) {
            int gi = min(r0 + r, 47);
            int src = srcb + gi*768;
            *(float4*)(Ks + r*3072 + dstb) = Kg4[src];
            *(float4*)(Vs + r*3072 + dstb) = Vg4[src];
        }
    }
    __syncthreads();

    // ---- attention
    int j = tid >> 4;
    int f = (tid >> 3) & 1;
    int h = tid & 7;
    int sj  = min(max(j - 3, 0), 41);

    int iqM = i0 + f;                      // my query row
    int iqO = i0 + (1 ^ f);                // partner's query row
    int dM  = min(max(iqM - 3, 0), 41) - r0;   // 0 or 1

    const float4* Q4 = (const float4*)g_Q;
    int qf4 = h*2 + f;                     // this half's channel float4
    float4 qM = Q4[(strip + iqM*48 + j)*16 + qf4];
    float4 qO = Q4[(strip + iqO*48 + j)*16 + qf4];

    float oMx=0,oMy=0,oMz=0,oMw=0;
    float oOx=0,oOy=0,oOz=0,oOw=0;
    float lM = 0.f;

    int chof = (f*8 + h)*4;
    const float* hb = rpb_s + h*169;
    int bcol = sj - j + 6;
    int briM = r0 - iqM + 6;

    #pragma unroll
    for (int r = 0; r < 8; r++) {
        float wM = ((unsigned)(r - dM) < 7u) ? 1.f : 0.f;
        const float* bM = hb + (briM + r)*13 + bcol;
        const float* kp = Ks + r*3072 + sj*64 + chof;
        const float* vp = Vs + r*3072 + sj*64 + chof;
        #pragma unroll
        for (int c = 0; c < 7; c++) {
            float4 k4 = *(const float4*)(kp + c*64);
            float4 v4 = *(const float4*)(vp + c*64);
            float spM = qM.x*k4.x + qM.y*k4.y + qM.z*k4.z + qM.w*k4.w;
            float spO = qO.x*k4.x + qO.y*k4.y + qO.z*k4.z + qO.w*k4.w;
            // partner sends the partial of MY query computed on ITS channels
            float sM = spM + __shfl_xor_sync(0xffffffffu, spO, 8);
            float eM = fexp(sM + bM[c]) * wM;
            float eO = __shfl_xor_sync(0xffffffffu, eM, 8);
            lM += eM;
            oMx = fmaf(eM, v4.x, oMx); oMy = fmaf(eM, v4.y, oMy);
            oMz = fmaf(eM, v4.z, oMz); oMw = fmaf(eM, v4.w, oMw);
            oOx = fmaf(eO, v4.x, oOx); oOy = fmaf(eO, v4.y, oOy);
            oOz = fmaf(eO, v4.z, oOz); oOw = fmaf(eO, v4.w, oOw);
        }
    }
    float lO = __shfl_xor_sync(0xffffffffu, lM, 8);
    __syncthreads();   // all Ks/Vs reads done; safe to alias

    // ---- write attention outputs to xout [96][64] (original channel order)
    {
        float invM = 1.f / lM, invO = 1.f / lO;
        float4 uM = make_float4(oMx*invM, oMy*invM, oMz*invM, oMw*invM);
        float4 uO = make_float4(oOx*invO, oOy*invO, oOz*invO, oOw*invO);
        int co = h*8 + f*4;                      // = (h*2+f)*4
        *(float4*)(xout + (f*48 + j)*64 + co)       = uM;
        *(float4*)(xout + ((1^f)*48 + j)*64 + co)   = uO;
    }
    // ---- stage proj weights [64][68]
    {
        const float4* pw4 = (const float4*)pw;
        for (int idx = tid; idx < 1024; idx += 768) {
            int cch = idx >> 4, qq = idx & 15;
            *(float4*)(pws + cch*68 + qq*4) = pw4[idx];
        }
    }
    __syncthreads();

    // ---- proj + LayerNorm: warp = 4 rows; lane = channels {lane, lane+32}
    int warp = tid >> 5, lane = tid & 31;
    int c0 = lane, c1 = lane + 32;
    const float4* w0p = (const float4*)(pws + c0*68);
    const float4* w1p = (const float4*)(pws + c1*68);
    float pb0 = __ldg(&pb[c0]),  pb1 = __ldg(&pb[c1]);
    float g0  = __ldg(&lng[c0]), g1  = __ldg(&lng[c1]);
    float bb0 = __ldg(&lnb[c0]), bb1 = __ldg(&lnb[c1]);
    int row0l = warp * 4;

    float y[4][2];
    #pragma unroll
    for (int rr = 0; rr < 4; rr++) { y[rr][0] = 0.f; y[rr][1] = 0.f; }

    #pragma unroll
    for (int cc = 0; cc < 16; cc++) {
        float4 wv0 = w0p[cc];
        float4 wv1 = w1p[cc];
        #pragma unroll
        for (int rr = 0; rr < 4; rr++) {
            float4 xv = *(const float4*)(xout + (row0l + rr)*64 + cc*4);
            y[rr][0] += xv.x*wv0.x + xv.y*wv0.y + xv.z*wv0.z + xv.w*wv0.w;
            y[rr][1] += xv.x*wv1.x + xv.y*wv1.y + xv.z*wv1.z + xv.w*wv1.w;
        }
    }

    #pragma unroll
    for (int rr = 0; rr < 4; rr++) {
        float y0 = y[rr][0] + pb0;
        float y1 = y[rr][1] + pb1;
        float s  = y0 + y1;
        float sq = y0*y0 + y1*y1;
        #pragma unroll
        for (int off = 16; off; off >>= 1) {
            s  += __shfl_xor_sync(0xffffffffu, s,  off);
            sq += __shfl_xor_sync(0xffffffffu, sq, off);
        }
        float mu  = s * (1.f/64.f);
        float var = sq * (1.f/64.f) - mu*mu;
        float rs  = rsqrtf(var + 1e-5f);

        int lr = row0l + rr;
        int irow = (lr >= 48);
        int pix = strip + (i0 + irow)*48 + (lr - irow*48);
        out[(size_t)pix*64 + c0] = (y0 - mu)*rs*g0 + bb0;
        out[(size_t)pix*64 + c1] = (y1 - mu)*rs*g1 + bb1;
    }
}

// ---------------------------------------------------------------------------
extern "C" void kernel_launch(void* const* d_in, const int* in_sizes, int n_in,
                              void* d_out, int out_size) {
    const float* q      = (const float*)d_in[0];
    const float* qkv_w  = (const float*)d_in[1];
    const float* qkv_b  = (const float*)d_in[2];
    const float* proj_w = (const float*)d_in[3];
    const float* proj_b = (const float*)d_in[4];
    const float* rpb    = (const float*)d_in[5];
    const float* ln_g   = (const float*)d_in[6];
    const float* ln_b   = (const float*)d_in[7];

    cudaFuncSetAttribute(qkv_kernel,
                         cudaFuncAttributeMaxDynamicSharedMemorySize, QKV_SMEM);
    cudaFuncSetAttribute(attn_proj_kernel,
                         cudaFuncAttributeMaxDynamicSharedMemorySize, ATTN_SMEM);

    qkv_kernel<<<dim3(NPIX/128, 2), 192, QKV_SMEM>>>(q, qkv_w, qkv_b);
    attn_proj_kernel<<<384, 768, ATTN_SMEM>>>(rpb, proj_w, proj_b,
                                              ln_g, ln_b, (float*)d_out);
}

// round 11
// speedup vs baseline: 2.4183x; 1.0500x over previous
#include <cuda_runtime.h>
#include <cuda_fp16.h>

#define BT 16
#define HH 48
#define WW 48
#define NPIX (BT*HH*WW)   /* 36864 */
#define QSCALE 0.35355339059327373f

// Scratch (static device allocations are allowed)
__device__ float g_Q[NPIX*64];
__device__ float g_K[NPIX*64];
__device__ float g_V[NPIX*64];

extern __shared__ float sdyn[];

// ---------------------------------------------------------------------------
// FMA-only exp (no MUFU), rel err ~2.4e-6
// ---------------------------------------------------------------------------
__device__ __forceinline__ float fexp(float x) {
    float z  = fmaf(x, 1.4426950408889634f, 12582912.0f);
    int   iz = __float_as_int(z);
    float n  = z - 12582912.0f;
    float f  = fmaf(n, -0.6931471805599453f, x);
    float p  = 8.3333333e-3f;
    p = fmaf(p, f, 4.1666667e-2f);
    p = fmaf(p, f, 1.6666667e-1f);
    p = fmaf(p, f, 5.0e-1f);
    p = fmaf(p, f, 1.0f);
    p = fmaf(p, f, 1.0f);
    return __int_as_float(__float_as_int(p) + (iz << 23));
}

// ---------------------------------------------------------------------------
// Kernel 1: QKV projection, register-tiled SGEMM (unchanged).
// ---------------------------------------------------------------------------
#define XPAD 132
#define WPAD 100
#define QKV_SMEM ((64*XPAD + 64*WPAD)*4)

__global__ __launch_bounds__(192) void qkv_kernel(const float* __restrict__ x,
                                                  const float* __restrict__ w,
                                                  const float* __restrict__ b) {
    float* xT = sdyn;              // [ch_slot][row 128]
    float* wT = sdyn + 64*XPAD;    // [ch_slot][col 96]
    int tid = threadIdx.x;
    int row0 = blockIdx.x * 128;
    int chunk = blockIdx.y * 96;

    const float4* x4 = (const float4*)(x + (size_t)row0*64);
    for (int idx = tid; idx < 128*16; idx += 192) {
        int r = idx >> 4, cq = idx & 15;
        float4 v = x4[idx];
        float vv[4] = {v.x, v.y, v.z, v.w};
        #pragma unroll
        for (int k = 0; k < 4; k++) {
            int s = cq*4 + ((k + cq) & 3);
            xT[s*XPAD + r] = vv[k];
        }
    }
    const float4* w4 = (const float4*)(w + (size_t)chunk*64);
    for (int idx = tid; idx < 96*16; idx += 192) {
        int o = idx >> 4, cq = idx & 15;
        float4 v = w4[idx];
        float vv[4] = {v.x, v.y, v.z, v.w};
        #pragma unroll
        for (int k = 0; k < 4; k++) {
            int s = cq*4 + ((k + cq) & 3);
            wT[s*WPAD + o] = vv[k];
        }
    }
    __syncthreads();

    int cx = tid % 12, ry = tid / 12;
    int r0 = ry*8, c0 = cx*8;

    float acc[8][8];
    #pragma unroll
    for (int i = 0; i < 8; i++)
        #pragma unroll
        for (int j = 0; j < 8; j++) acc[i][j] = 0.f;

    #pragma unroll 4
    for (int s = 0; s < 64; s++) {
        float4 xa = *(const float4*)&xT[s*XPAD + r0];
        float4 xb = *(const float4*)&xT[s*XPAD + r0 + 4];
        float4 wa = *(const float4*)&wT[s*WPAD + c0];
        float4 wb = *(const float4*)&wT[s*WPAD + c0 + 4];
        float xr[8] = {xa.x,xa.y,xa.z,xa.w, xb.x,xb.y,xb.z,xb.w};
        float wc[8] = {wa.x,wa.y,wa.z,wa.w, wb.x,wb.y,wb.z,wb.w};
        #pragma unroll
        for (int i = 0; i < 8; i++)
            #pragma unroll
            for (int j = 0; j < 8; j++)
                acc[i][j] = fmaf(xr[i], wc[j], acc[i][j]);
    }

    int oc = chunk + c0;
    float bias[8];
    *(float4*)&bias[0] = __ldg((const float4*)(b + oc));
    *(float4*)&bias[4] = __ldg((const float4*)(b + oc + 4));
    float scale = (oc < 64) ? QSCALE : 1.f;
    float* dstbase = (oc < 64) ? g_Q : (oc < 128 ? g_K : g_V);
    int cc0 = oc & 63;
    #pragma unroll
    for (int i = 0; i < 8; i++) {
        size_t rb = (size_t)(row0 + r0 + i)*64 + cc0;
        float4 o0, o1;
        o0.x = (acc[i][0]+bias[0])*scale; o0.y = (acc[i][1]+bias[1])*scale;
        o0.z = (acc[i][2]+bias[2])*scale; o0.w = (acc[i][3]+bias[3])*scale;
        o1.x = (acc[i][4]+bias[4])*scale; o1.y = (acc[i][5]+bias[5])*scale;
        o1.z = (acc[i][6]+bias[6])*scale; o1.w = (acc[i][7]+bias[7])*scale;
        *(float4*)&dstbase[rb]     = o0;
        *(float4*)&dstbase[rb + 4] = o1;
    }
}

// ---------------------------------------------------------------------------
// Kernel 2: attention (fp16 K/V smem, query-ownership softmax) + proj + LN.
// Block = 768 threads = (j, head, half). smem ~101KB -> 2 blocks/SM.
// K/V tile stored as half2, slot-permuted: pixel stride 128B,
// slot (f*8+h) holds 4 channels (8B). LDS.64 conflict-free per half-warp.
// ---------------------------------------------------------------------------
#define KV_H2   (8*48*32)            /* half2 per array: 12288 (=49152 B) */
#define RPB_OFFB (2*KV_H2*4)         /* byte offset of rpb: 98304 */
#define ATTN_SMEM (RPB_OFFB + 8*169*4 + 256)

__global__ __launch_bounds__(768, 2) void attn_proj_kernel(const float* __restrict__ rpb,
                                                        const float* __restrict__ pw,
                                                        const float* __restrict__ pb,
                                                        const float* __restrict__ lng,
                                                        const float* __restrict__ lnb,
                                                        float* __restrict__ out) {
    __half2* Ksh  = (__half2*)sdyn;
    __half2* Vsh  = (__half2*)sdyn + KV_H2;
    float* rpb_s  = (float*)((char*)sdyn + RPB_OFFB);
    float* xout   = sdyn;                    // alias over K region: [96][64] f32
    float* pws    = sdyn + 12288;            // alias over V region: [64][68] f32

    int tid = threadIdx.x;
    int blk = blockIdx.x;
    int bt = blk / 24, i0 = (blk % 24) * 2;
    int strip = bt * 2304;

    for (int idx = tid; idx < 8*169; idx += 768) rpb_s[idx] = rpb[idx];

    // ---- stage K/V as fp16, slot-permuted (STS.64, conflict-free)
    int r0 = min(max(i0 - 3, 0), 41);
    {
        const float4* Kg4 = (const float4*)g_K;
        const float4* Vg4 = (const float4*)g_V;
        int c = tid >> 4, s = tid & 15;
        int q = ((s & 7) << 1) | (s >> 3);       // src float4 for dst slot s
        int dstb = c*32 + s*2;                    // half2 index within row
        int srcb = (strip + c)*16 + q;
        #pragma unroll
        for (int r = 0; r < 8; r++) {
            int gi = min(r0 + r, 47);
            int src = srcb + gi*768;
            float4 kv = Kg4[src];
            float4 vv = Vg4[src];
            __half2 k0 = __floats2half2_rn(kv.x, kv.y);
            __half2 k1 = __floats2half2_rn(kv.z, kv.w);
            __half2 v0 = __floats2half2_rn(vv.x, vv.y);
            __half2 v1 = __floats2half2_rn(vv.z, vv.w);
            *(uint2*)(Ksh + r*1536 + dstb) = make_uint2(*(unsigned*)&k0, *(unsigned*)&k1);
            *(uint2*)(Vsh + r*1536 + dstb) = make_uint2(*(unsigned*)&v0, *(unsigned*)&v1);
        }
    }
    __syncthreads();

    // ---- attention
    int j = tid >> 4;
    int f = (tid >> 3) & 1;
    int h = tid & 7;
    int sj  = min(max(j - 3, 0), 41);

    int iqM = i0 + f;                      // my query row
    int iqO = i0 + (1 ^ f);                // partner's query row
    int dM  = min(max(iqM - 3, 0), 41) - r0;   // 0 or 1

    const float4* Q4 = (const float4*)g_Q;
    int qf4 = h*2 + f;
    float4 qM = Q4[(strip + iqM*48 + j)*16 + qf4];
    float4 qO = Q4[(strip + iqO*48 + j)*16 + qf4];

    float oMx=0,oMy=0,oMz=0,oMw=0;
    float oOx=0,oOy=0,oOz=0,oOw=0;
    float lM = 0.f;

    int slot2 = (f*8 + h)*2;               // half2 offset of this half's 4 ch
    const float* hb = rpb_s + h*169;
    int bcol = sj - j + 6;
    int briM = r0 - iqM + 6;

    #pragma unroll 2
    for (int r = 0; r < 8; r++) {
        float wM = ((unsigned)(r - dM) < 7u) ? 1.f : 0.f;
        const float* bM = hb + (briM + r)*13 + bcol;
        const __half2* kp = Ksh + r*1536 + sj*32 + slot2;
        const __half2* vp = Vsh + r*1536 + sj*32 + slot2;
        #pragma unroll
        for (int c = 0; c < 7; c++) {
            uint2 kr = *(const uint2*)(kp + c*32);
            uint2 vr = *(const uint2*)(vp + c*32);
            float2 ka = __half22float2(*(__half2*)&kr.x);
            float2 kb = __half22float2(*(__half2*)&kr.y);
            float2 va = __half22float2(*(__half2*)&vr.x);
            float2 vb = __half22float2(*(__half2*)&vr.y);
            float spM = qM.x*ka.x + qM.y*ka.y + qM.z*kb.x + qM.w*kb.y;
            float spO = qO.x*ka.x + qO.y*ka.y + qO.z*kb.x + qO.w*kb.y;
            float sM = spM + __shfl_xor_sync(0xffffffffu, spO, 8);
            float eM = fexp(sM + bM[c]) * wM;
            float eO = __shfl_xor_sync(0xffffffffu, eM, 8);
            lM += eM;
            oMx = fmaf(eM, va.x, oMx); oMy = fmaf(eM, va.y, oMy);
            oMz = fmaf(eM, vb.x, oMz); oMw = fmaf(eM, vb.y, oMw);
            oOx = fmaf(eO, va.x, oOx); oOy = fmaf(eO, va.y, oOy);
            oOz = fmaf(eO, vb.x, oOz); oOw = fmaf(eO, vb.y, oOw);
        }
    }
    float lO = __shfl_xor_sync(0xffffffffu, lM, 8);
    __syncthreads();   // all Ksh/Vsh reads done; safe to alias

    // ---- write attention outputs to xout [96][64]
    {
        float invM = 1.f / lM, invO = 1.f / lO;
        float4 uM = make_float4(oMx*invM, oMy*invM, oMz*invM, oMw*invM);
        float4 uO = make_float4(oOx*invO, oOy*invO, oOz*invO, oOw*invO);
        int co = h*8 + f*4;
        *(float4*)(xout + (f*48 + j)*64 + co)     = uM;
        *(float4*)(xout + ((1^f)*48 + j)*64 + co) = uO;
    }
    // ---- stage proj weights [64][68]
    {
        const float4* pw4 = (const float4*)pw;
        for (int idx = tid; idx < 1024; idx += 768) {
            int cch = idx >> 4, qq = idx & 15;
            *(float4*)(pws + cch*68 + qq*4) = pw4[idx];
        }
    }
    __syncthreads();

    // ---- proj + LayerNorm: warp = 4 rows; lane = channels {lane, lane+32}
    int warp = tid >> 5, lane = tid & 31;
    int c0 = lane, c1 = lane + 32;
    const float4* w0p = (const float4*)(pws + c0*68);
    const float4* w1p = (const float4*)(pws + c1*68);
    float pb0 = __ldg(&pb[c0]),  pb1 = __ldg(&pb[c1]);
    float g0  = __ldg(&lng[c0]), g1  = __ldg(&lng[c1]);
    float bb0 = __ldg(&lnb[c0]), bb1 = __ldg(&lnb[c1]);
    int row0l = warp * 4;

    float y[4][2];
    #pragma unroll
    for (int rr = 0; rr < 4; rr++) { y[rr][0] = 0.f; y[rr][1] = 0.f; }

    #pragma unroll
    for (int cc = 0; cc < 16; cc++) {
        float4 wv0 = w0p[cc];
        float4 wv1 = w1p[cc];
        #pragma unroll
        for (int rr = 0; rr < 4; rr++) {
            float4 xv = *(const float4*)(xout + (row0l + rr)*64 + cc*4);
            y[rr][0] += xv.x*wv0.x + xv.y*wv0.y + xv.z*wv0.z + xv.w*wv0.w;
            y[rr][1] += xv.x*wv1.x + xv.y*wv1.y + xv.z*wv1.z + xv.w*wv1.w;
        }
    }

    #pragma unroll
    for (int rr = 0; rr < 4; rr++) {
        float y0 = y[rr][0] + pb0;
        float y1 = y[rr][1] + pb1;
        float s  = y0 + y1;
        float sq = y0*y0 + y1*y1;
        #pragma unroll
        for (int off = 16; off; off >>= 1) {
            s  += __shfl_xor_sync(0xffffffffu, s,  off);
            sq += __shfl_xor_sync(0xffffffffu, sq, off);
        }
        float mu  = s * (1.f/64.f);
        float var = sq * (1.f/64.f) - mu*mu;
        float rs  = rsqrtf(var + 1e-5f);

        int lr = row0l + rr;
        int irow = (lr >= 48);
        int pix = strip + (i0 + irow)*48 + (lr - irow*48);
        out[(size_t)pix*64 + c0] = (y0 - mu)*rs*g0 + bb0;
        out[(size_t)pix*64 + c1] = (y1 - mu)*rs*g1 + bb1;
    }
}

// ---------------------------------------------------------------------------
extern "C" void kernel_launch(void* const* d_in, const int* in_sizes, int n_in,
                              void* d_out, int out_size) {
    const float* q      = (const float*)d_in[0];
    const float* qkv_w  = (const float*)d_in[1];
    const float* qkv_b  = (const float*)d_in[2];
    const float* proj_w = (const float*)d_in[3];
    const float* proj_b = (const float*)d_in[4];
    const float* rpb    = (const float*)d_in[5];
    const float* ln_g   = (const float*)d_in[6];
    const float* ln_b   = (const float*)d_in[7];

    cudaFuncSetAttribute(qkv_kernel,
                         cudaFuncAttributeMaxDynamicSharedMemorySize, QKV_SMEM);
    cudaFuncSetAttribute(attn_proj_kernel,
                         cudaFuncAttributeMaxDynamicSharedMemorySize, ATTN_SMEM);

    qkv_kernel<<<dim3(NPIX/128, 2), 192, QKV_SMEM>>>(q, qkv_w, qkv_b);
    attn_proj_kernel<<<384, 768, ATTN_SMEM>>>(rpb, proj_w, proj_b,
                                              ln_g, ln_b, (float*)d_out);
}

// round 14
// speedup vs baseline: 2.5562x; 1.0570x over previous
#include <cuda_runtime.h>
#include <cuda_fp16.h>

#define BT 16
#define HH 48
#define WW 48
#define NPIX (BT*HH*WW)   /* 36864 */
#define QSCALE 0.35355339059327373f

// Scratch (static device allocations are allowed)
__device__ float g_Q[NPIX*64];
__device__ float g_K[NPIX*64];
__device__ float g_V[NPIX*64];

extern __shared__ float sdyn[];

// ---------------------------------------------------------------------------
// FMA-only exp (no MUFU), rel err ~2.4e-6
// ---------------------------------------------------------------------------
__device__ __forceinline__ float fexp(float x) {
    float z  = fmaf(x, 1.4426950408889634f, 12582912.0f);
    int   iz = __float_as_int(z);
    float n  = z - 12582912.0f;
    float f  = fmaf(n, -0.6931471805599453f, x);
    float p  = 8.3333333e-3f;
    p = fmaf(p, f, 4.1666667e-2f);
    p = fmaf(p, f, 1.6666667e-1f);
    p = fmaf(p, f, 5.0e-1f);
    p = fmaf(p, f, 1.0f);
    p = fmaf(p, f, 1.0f);
    return __int_as_float(__float_as_int(p) + (iz << 23));
}

// ---------------------------------------------------------------------------
// Kernel 1: QKV projection, register-tiled SGEMM (unchanged).
// ---------------------------------------------------------------------------
#define XPAD 132
#define WPAD 100
#define QKV_SMEM ((64*XPAD + 64*WPAD)*4)

__global__ __launch_bounds__(192) void qkv_kernel(const float* __restrict__ x,
                                                  const float* __restrict__ w,
                                                  const float* __restrict__ b) {
    float* xT = sdyn;              // [ch_slot][row 128]
    float* wT = sdyn + 64*XPAD;    // [ch_slot][col 96]
    int tid = threadIdx.x;
    int row0 = blockIdx.x * 128;
    int chunk = blockIdx.y * 96;

    const float4* x4 = (const float4*)(x + (size_t)row0*64);
    for (int idx = tid; idx < 128*16; idx += 192) {
        int r = idx >> 4, cq = idx & 15;
        float4 v = x4[idx];
        float vv[4] = {v.x, v.y, v.z, v.w};
        #pragma unroll
        for (int k = 0; k < 4; k++) {
            int s = cq*4 + ((k + cq) & 3);
            xT[s*XPAD + r] = vv[k];
        }
    }
    const float4* w4 = (const float4*)(w + (size_t)chunk*64);
    for (int idx = tid; idx < 96*16; idx += 192) {
        int o = idx >> 4, cq = idx & 15;
        float4 v = w4[idx];
        float vv[4] = {v.x, v.y, v.z, v.w};
        #pragma unroll
        for (int k = 0; k < 4; k++) {
            int s = cq*4 + ((k + cq) & 3);
            wT[s*WPAD + o] = vv[k];
        }
    }
    __syncthreads();

    int cx = tid % 12, ry = tid / 12;
    int r0 = ry*8, c0 = cx*8;

    float acc[8][8];
    #pragma unroll
    for (int i = 0; i < 8; i++)
        #pragma unroll
        for (int j = 0; j < 8; j++) acc[i][j] = 0.f;

    #pragma unroll 4
    for (int s = 0; s < 64; s++) {
        float4 xa = *(const float4*)&xT[s*XPAD + r0];
        float4 xb = *(const float4*)&xT[s*XPAD + r0 + 4];
        float4 wa = *(const float4*)&wT[s*WPAD + c0];
        float4 wb = *(const float4*)&wT[s*WPAD + c0 + 4];
        float xr[8] = {xa.x,xa.y,xa.z,xa.w, xb.x,xb.y,xb.z,xb.w};
        float wc[8] = {wa.x,wa.y,wa.z,wa.w, wb.x,wb.y,wb.z,wb.w};
        #pragma unroll
        for (int i = 0; i < 8; i++)
            #pragma unroll
            for (int j = 0; j < 8; j++)
                acc[i][j] = fmaf(xr[i], wc[j], acc[i][j]);
    }

    int oc = chunk + c0;
    float bias[8];
    *(float4*)&bias[0] = __ldg((const float4*)(b + oc));
    *(float4*)&bias[4] = __ldg((const float4*)(b + oc + 4));
    float scale = (oc < 64) ? QSCALE : 1.f;
    float* dstbase = (oc < 64) ? g_Q : (oc < 128 ? g_K : g_V);
    int cc0 = oc & 63;
    #pragma unroll
    for (int i = 0; i < 8; i++) {
        size_t rb = (size_t)(row0 + r0 + i)*64 + cc0;
        float4 o0, o1;
        o0.x = (acc[i][0]+bias[0])*scale; o0.y = (acc[i][1]+bias[1])*scale;
        o0.z = (acc[i][2]+bias[2])*scale; o0.w = (acc[i][3]+bias[3])*scale;
        o1.x = (acc[i][4]+bias[4])*scale; o1.y = (acc[i][5]+bias[5])*scale;
        o1.z = (acc[i][6]+bias[6])*scale; o1.w = (acc[i][7]+bias[7])*scale;
        *(float4*)&dstbase[rb]     = o0;
        *(float4*)&dstbase[rb + 4] = o1;
    }
}

// ---------------------------------------------------------------------------
// Kernel 2: attention (fp16 K/V smem; full-dot query ownership; HFMA2 dot)
// + proj + LN. Block = 768 threads = (j, head, half f). Thread owns query
// row i0+f: full 8-ch dot via half2 FMA (K head-contiguous, LDS.128
// broadcast across the f-pair), 1 fexp, 1 shfl (e exchange). V split 4+4.
// smem ~99KB -> 2 blocks/SM.
// ---------------------------------------------------------------------------
#define KV_H2   (8*48*32)            /* half2 per array: 12288 (=49152 B) */
#define RPB_OFFB (2*KV_H2*4)         /* byte offset of rpb: 98304 */
#define ATTN_SMEM (RPB_OFFB + 8*169*4 + 256)

__global__ __launch_bounds__(768, 2) void attn_proj_kernel(const float* __restrict__ rpb,
                                                        const float* __restrict__ pw,
                                                        const float* __restrict__ pb,
                                                        const float* __restrict__ lng,
                                                        const float* __restrict__ lnb,
                                                        float* __restrict__ out) {
    __half2* Ksh  = (__half2*)sdyn;              // [r][pix][h*4 half2] head-contig
    __half2* Vsh  = (__half2*)sdyn + KV_H2;      // [r][pix][(f*8+h)*2 half2]
    float* rpb_s  = (float*)((char*)sdyn + RPB_OFFB);
    float* xout   = sdyn;                    // alias over K region: [96][64] f32
    float* pws    = sdyn + 12288;            // alias over V region: [64][68] f32

    int tid = threadIdx.x;
    int blk = blockIdx.x;
    int bt = blk / 24, i0 = (blk % 24) * 2;
    int strip = bt * 2304;

    for (int idx = tid; idx < 8*169; idx += 768) rpb_s[idx] = rpb[idx];

    // ---- stage K/V as fp16 (8B stores, conflict-free)
    // K: slot s (=h*2+part) -> half2 idx s*2 (channels in order)
    // V: slot s -> half2 idx ((s&1)*8 + (s>>1))*2  (split by half f=part)
    int r0 = min(max(i0 - 3, 0), 41);
    {
        const float4* Kg4 = (const float4*)g_K;
        const float4* Vg4 = (const float4*)g_V;
        int c = tid >> 4, s = tid & 15;
        int kdst = c*32 + s*2;
        int vdst = c*32 + ((s & 1)*8 + (s >> 1))*2;
        int srcb = (strip + c)*16 + s;
        #pragma unroll
        for (int r = 0; r < 8; r++) {
            int gi = min(r0 + r, 47);
            int src = srcb + gi*768;
            float4 kv = Kg4[src];
            float4 vv = Vg4[src];
            __half2 k0 = __floats2half2_rn(kv.x, kv.y);
            __half2 k1 = __floats2half2_rn(kv.z, kv.w);
            __half2 v0 = __floats2half2_rn(vv.x, vv.y);
            __half2 v1 = __floats2half2_rn(vv.z, vv.w);
            *(uint2*)(Ksh + r*1536 + kdst) = make_uint2(*(unsigned*)&k0, *(unsigned*)&k1);
            *(uint2*)(Vsh + r*1536 + vdst) = make_uint2(*(unsigned*)&v0, *(unsigned*)&v1);
        }
    }
    __syncthreads();

    // ---- attention
    int j = tid >> 4;
    int f = (tid >> 3) & 1;
    int h = tid & 7;
    int sj  = min(max(j - 3, 0), 41);

    int iqM = i0 + f;                          // my query row
    int dM  = min(max(iqM - 3, 0), 41) - r0;   // 0 or 1

    // my query, all 8 channels, as 4x half2
    const float4* Q4 = (const float4*)g_Q;
    float4 qa = Q4[(strip + iqM*48 + j)*16 + h*2];
    float4 qb = Q4[(strip + iqM*48 + j)*16 + h*2 + 1];
    __half2 qh0 = __floats2half2_rn(qa.x, qa.y);
    __half2 qh1 = __floats2half2_rn(qa.z, qa.w);
    __half2 qh2 = __floats2half2_rn(qb.x, qb.y);
    __half2 qh3 = __floats2half2_rn(qb.z, qb.w);

    float oMx=0,oMy=0,oMz=0,oMw=0;
    float oOx=0,oOy=0,oOz=0,oOw=0;
    float lM = 0.f;

    const float* hb = rpb_s + h*169;
    int bcol = sj - j + 6;
    int briM = r0 - iqM + 6;
    int kofs = h*4;                    // half2 offset of my head's 8 channels
    int vofs = (f*8 + h)*2;            // half2 offset of my 4 V channels

    #pragma unroll 2
    for (int r = 0; r < 8; r++) {
        float wM = ((unsigned)(r - dM) < 7u) ? 1.f : 0.f;
        const float* bM = hb + (briM + r)*13 + bcol;
        const __half2* kp = Ksh + r*1536 + sj*32 + kofs;
        const __half2* vp = Vsh + r*1536 + sj*32 + vofs;
        #pragma unroll
        for (int c = 0; c < 7; c++) {
            uint4 kr = *(const uint4*)(kp + c*32);
            uint2 vr = *(const uint2*)(vp + c*32);
            __half2 p0 = __hmul2(qh0, *(__half2*)&kr.x);
            __half2 p1 = __hmul2(qh1, *(__half2*)&kr.y);
            p0 = __hfma2(qh2, *(__half2*)&kr.z, p0);
            p1 = __hfma2(qh3, *(__half2*)&kr.w, p1);
            p0 = __hadd2(p0, p1);
            float2 pf = __half22float2(p0);
            float eM = fexp(pf.x + pf.y + bM[c]) * wM;
            float eO = __shfl_xor_sync(0xffffffffu, eM, 8);
            lM += eM;
            float2 va = __half22float2(*(__half2*)&vr.x);
            float2 vb = __half22float2(*(__half2*)&vr.y);
            oMx = fmaf(eM, va.x, oMx); oMy = fmaf(eM, va.y, oMy);
            oMz = fmaf(eM, vb.x, oMz); oMw = fmaf(eM, vb.y, oMw);
            oOx = fmaf(eO, va.x, oOx); oOy = fmaf(eO, va.y, oOy);
            oOz = fmaf(eO, vb.x, oOz); oOw = fmaf(eO, vb.y, oOw);
        }
    }
    float lO = __shfl_xor_sync(0xffffffffu, lM, 8);
    __syncthreads();   // all Ksh/Vsh reads done; safe to alias

    // ---- write attention outputs to xout [96][64]
    {
        float invM = 1.f / lM, invO = 1.f / lO;
        float4 uM = make_float4(oMx*invM, oMy*invM, oMz*invM, oMw*invM);
        float4 uO = make_float4(oOx*invO, oOy*invO, oOz*invO, oOw*invO);
        int co = h*8 + f*4;
        *(float4*)(xout + (f*48 + j)*64 + co)     = uM;
        *(float4*)(xout + ((1^f)*48 + j)*64 + co) = uO;
    }
    // ---- stage proj weights [64][68]
    {
        const float4* pw4 = (const float4*)pw;
        for (int idx = tid; idx < 1024; idx += 768) {
            int cch = idx >> 4, qq = idx & 15;
            *(float4*)(pws + cch*68 + qq*4) = pw4[idx];
        }
    }
    __syncthreads();

    // ---- proj + LayerNorm: warp = 4 rows; lane = channels {lane, lane+32}
    int warp = tid >> 5, lane = tid & 31;
    int c0 = lane, c1 = lane + 32;
    const float4* w0p = (const float4*)(pws + c0*68);
    const float4* w1p = (const float4*)(pws + c1*68);
    float pb0 = __ldg(&pb[c0]),  pb1 = __ldg(&pb[c1]);
    float g0  = __ldg(&lng[c0]), g1  = __ldg(&lng[c1]);
    float bb0 = __ldg(&lnb[c0]), bb1 = __ldg(&lnb[c1]);
    int row0l = warp * 4;

    float y[4][2];
    #pragma unroll
    for (int rr = 0; rr < 4; rr++) { y[rr][0] = 0.f; y[rr][1] = 0.f; }

    #pragma unroll
    for (int cc = 0; cc < 16; cc++) {
        float4 wv0 = w0p[cc];
        float4 wv1 = w1p[cc];
        #pragma unroll
        for (int rr = 0; rr < 4; rr++) {
            float4 xv = *(const float4*)(xout + (row0l + rr)*64 + cc*4);
            y[rr][0] += xv.x*wv0.x + xv.y*wv0.y + xv.z*wv0.z + xv.w*wv0.w;
            y[rr][1] += xv.x*wv1.x + xv.y*wv1.y + xv.z*wv1.z + xv.w*wv1.w;
        }
    }

    #pragma unroll
    for (int rr = 0; rr < 4; rr++) {
        float y0 = y[rr][0] + pb0;
        float y1 = y[rr][1] + pb1;
        float s  = y0 + y1;
        float sq = y0*y0 + y1*y1;
        #pragma unroll
        for (int off = 16; off; off >>= 1) {
            s  += __shfl_xor_sync(0xffffffffu, s,  off);
            sq += __shfl_xor_sync(0xffffffffu, sq, off);
        }
        float mu  = s * (1.f/64.f);
        float var = sq * (1.f/64.f) - mu*mu;
        float rs  = rsqrtf(var + 1e-5f);

        int lr = row0l + rr;
        int irow = (lr >= 48);
        int pix = strip + (i0 + irow)*48 + (lr - irow*48);
        out[(size_t)pix*64 + c0] = (y0 - mu)*rs*g0 + bb0;
        out[(size_t)pix*64 + c1] = (y1 - mu)*rs*g1 + bb1;
    }
}

// ---------------------------------------------------------------------------
extern "C" void kernel_launch(void* const* d_in, const int* in_sizes, int n_in,
                              void* d_out, int out_size) {
    const float* q      = (const float*)d_in[0];
    const float* qkv_w  = (const float*)d_in[1];
    const float* qkv_b  = (const float*)d_in[2];
    const float* proj_w = (const float*)d_in[3];
    const float* proj_b = (const float*)d_in[4];
    const float* rpb    = (const float*)d_in[5];
    const float* ln_g   = (const float*)d_in[6];
    const float* ln_b   = (const float*)d_in[7];

    cudaFuncSetAttribute(qkv_kernel,
                         cudaFuncAttributeMaxDynamicSharedMemorySize, QKV_SMEM);
    cudaFuncSetAttribute(attn_proj_kernel,
                         cudaFuncAttributeMaxDynamicSharedMemorySize, ATTN_SMEM);

    qkv_kernel<<<dim3(NPIX/128, 2), 192, QKV_SMEM>>>(q, qkv_w, qkv_b);
    attn_proj_kernel<<<384, 768, ATTN_SMEM>>>(rpb, proj_w, proj_b,
                                              ln_g, ln_b, (float*)d_out);
}